// round 9
// baseline (speedup 1.0000x reference)
#include <cuda_runtime.h>
#include <cuda_bf16.h>
#include <cstdint>

#define B_   16
#define N_   4096
#define C_   64
#define S_   1024
#define K0_  16
#define K1_  32
#define M0_  (B_ * S_ * K0_)   // 262144
#define M1_  (B_ * S_ * K1_)   // 524288
#define R0SQ 0.01f
#define R1SQ 0.04f
#define EPS_ 1e-5f

// ---------------- scratch (device globals, zero-init) ----------------
__device__ float g_fp0[B_ * N_ * C_];
__device__ float g_fp1[B_ * N_ * C_];
__device__ int   g_idx0[B_ * S_ * K0_];
__device__ int   g_idx1[B_ * S_ * K1_];
__device__ float g_a0[64u * 262144u];
__device__ float g_b0[64u * 262144u];
__device__ float g_a1[64u * 524288u];
__device__ float g_b1[96u * 524288u];
__device__ float g_gmx0[16384u * 128u];
__device__ float g_gmn0[16384u * 128u];
__device__ float g_gmx1[16384u * 128u];
__device__ float g_gmn1[16384u * 128u];
__device__ float g_stats0[256];
__device__ float g_affine0[256];
__device__ float g_stats1[256];
__device__ float g_affine1[256];

__device__ __forceinline__ float f2tf_f(float x) {
    uint32_t r;
    asm("cvt.rna.tf32.f32 %0, %1;" : "=r"(r) : "f"(x));
    return __uint_as_float(r);
}

__device__ __forceinline__ void mma_tf32(float* d, const uint32_t* a, const uint32_t* b) {
    asm volatile("mma.sync.aligned.m16n8k8.row.col.f32.tf32.tf32.f32 "
                 "{%0,%1,%2,%3}, {%4,%5,%6,%7}, {%8,%9}, {%0,%1,%2,%3};"
                 : "+f"(d[0]), "+f"(d[1]), "+f"(d[2]), "+f"(d[3])
                 : "r"(a[0]), "r"(a[1]), "r"(a[2]), "r"(a[3]), "r"(b[0]), "r"(b[1]));
}

// ---------------- FPS (redux-based reduction) ----------------
__global__ void fps_kernel(const float* __restrict__ xyz, float* __restrict__ newxyz)
{
    extern __shared__ float sm[];
    float* sx = sm; float* sy = sm + N_; float* sz = sm + 2 * N_;
    __shared__ unsigned sbits[2][32];
    __shared__ int      sidx[2][32];

    const int b = blockIdx.x;
    const int t = threadIdx.x;          // 1024
    const int lane = t & 31, wid = t >> 5;

    for (int i = t; i < N_; i += 1024) {
        const float* p = xyz + ((size_t)b * N_ + i) * 3;
        sx[i] = p[0]; sy[i] = p[1]; sz[i] = p[2];
    }
    __syncthreads();

    float px[4], py[4], pz[4], dist[4];
#pragma unroll
    for (int j = 0; j < 4; ++j) {
        int n = t + (j << 10);
        px[j] = sx[n]; py[j] = sy[n]; pz[j] = sz[n];
        dist[j] = 1e10f;
    }

    if (t == 0) {
        float* o = newxyz + (size_t)b * S_ * 3;
        o[0] = sx[0]; o[1] = sy[0]; o[2] = sz[0];
    }
    float lx = sx[0], ly = sy[0], lz = sz[0];

    int p_ = 0;
    for (int i = 1; i < S_; ++i) {
        float bv = -1.0f; int bi = 0;
#pragma unroll
        for (int j = 0; j < 4; ++j) {
            float dx = px[j] - lx, dy = py[j] - ly, dz = pz[j] - lz;
            float d = dx * dx + dy * dy + dz * dz;
            float nd = fminf(dist[j], d);
            dist[j] = nd;
            if (nd > bv) { bv = nd; bi = t + (j << 10); }
        }
        unsigned dbits = __float_as_uint(bv);
        unsigned wmax = __reduce_max_sync(0xffffffffu, dbits);
        unsigned cand = (dbits == wmax) ? (unsigned)bi : 0xffffffffu;
        unsigned widx = __reduce_min_sync(0xffffffffu, cand);
        if (lane == 0) { sbits[p_][wid] = wmax; sidx[p_][wid] = (int)widx; }
        __syncthreads();
        unsigned vb = sbits[p_][lane];
        int      vi = sidx[p_][lane];
        unsigned bmax = __reduce_max_sync(0xffffffffu, vb);
        unsigned c2 = (vb == bmax) ? (unsigned)vi : 0xffffffffu;
        int bsel = (int)__reduce_min_sync(0xffffffffu, c2);
        lx = sx[bsel]; ly = sy[bsel]; lz = sz[bsel];
        if (t == 0) {
            float* o = newxyz + ((size_t)b * S_ + i) * 3;
            o[0] = lx; o[1] = ly; o[2] = lz;
        }
        p_ ^= 1;
    }
}

// ---------------- combined feature pre-GEMM (both scales, one feat pass) ----------------
__global__ __launch_bounds__(256) void featgemm2_kernel(
    const float* __restrict__ feat,
    const float* __restrict__ W0, const float* __restrict__ W1,
    float* __restrict__ Fp0, float* __restrict__ Fp1)
{
    extern __shared__ float sm[];
    float* Wt = sm;             // [64][65]
    float* Xs = Wt + 64 * 65;   // [64][128]
    const int tid = threadIdx.x;
    const int b = blockIdx.y;
    const int n0 = blockIdx.x * 128;

    for (int i = tid; i < 64 * 32; i += 256) {
        int k = i >> 5, q = i & 31;
        *(float4*)(Xs + k * 128 + q * 4) =
            *(const float4*)(feat + ((size_t)(b * 64 + k)) * N_ + n0 + q * 4);
    }

    const int mi = tid & 15, ci = tid >> 4;
#pragma unroll
    for (int s = 0; s < 2; ++s) {
        const float* W = s ? W1 : W0;
        float* Fp = s ? Fp1 : Fp0;
        __syncthreads();
        for (int i = tid; i < 64 * 64; i += 256) {
            int co = i >> 6, k = i & 63;
            Wt[k * 65 + co] = W[co * 67 + 3 + k];
        }
        __syncthreads();

        float acc[4][8];
#pragma unroll
        for (int j = 0; j < 4; ++j)
#pragma unroll
            for (int r = 0; r < 8; ++r) acc[j][r] = 0.0f;

#pragma unroll 4
        for (int k = 0; k < 64; ++k) {
            float xf[8];
            *(float4*)xf       = *(const float4*)(Xs + k * 128 + mi * 8);
            *(float4*)(xf + 4) = *(const float4*)(Xs + k * 128 + mi * 8 + 4);
#pragma unroll
            for (int j = 0; j < 4; ++j) {
                float w = Wt[k * 65 + ci * 4 + j];
#pragma unroll
                for (int r = 0; r < 8; ++r) acc[j][r] = fmaf(w, xf[r], acc[j][r]);
            }
        }
#pragma unroll
        for (int r = 0; r < 8; ++r) {
            size_t row = (size_t)(b << 12) + n0 + mi * 8 + r;
            *(float4*)(Fp + (row << 6) + ci * 4) =
                make_float4(acc[0][r], acc[1][r], acc[2][r], acc[3][r]);
        }
    }
}

// ---------------- fused ball query (conditional ballots) ----------------
__global__ void ballquery_kernel(const float* __restrict__ xyz,
                                 const float* __restrict__ newxyz,
                                 int* __restrict__ idx0, int* __restrict__ idx1)
{
    __shared__ float sx[N_], sy[N_], sz[N_];
    const int bb = blockIdx.y;
    const int tid = threadIdx.x;                 // 512
    const int lane = tid & 31, w = tid >> 5;

    for (int i = tid; i < N_ * 3; i += 512) {
        float v = xyz[(size_t)bb * N_ * 3 + i];
        int n = i / 3, d = i - n * 3;
        if (d == 0) sx[n] = v; else if (d == 1) sy[n] = v; else sz[n] = v;
    }
    __syncthreads();

    const unsigned ltmask = (1u << lane) - 1u;

    for (int cc = 0; cc < 4; ++cc) {
        int s_ = blockIdx.x * 64 + w * 4 + cc;
        const float* ctr = newxyz + ((size_t)bb * S_ + s_) * 3;
        float cx = ctr[0], cy = ctr[1], cz = ctr[2];
        int* o0 = idx0 + ((size_t)bb * S_ + s_) * K0_;
        int* o1 = idx1 + ((size_t)bb * S_ + s_) * K1_;
        int cnt0 = 0, cnt1 = 0, first0 = 0, first1 = 0;

        for (int base = 0; base < N_; base += 32) {
            int n = base + lane;
            float dx = sx[n] - cx, dy = sy[n] - cy, dz = sz[n] - cz;
            float d2 = dx * dx + dy * dy + dz * dz;
            if (cnt1 < K1_) {
                unsigned m1 = __ballot_sync(0xffffffffu, d2 < R1SQ);
                if (m1) {
                    if (cnt1 == 0) first1 = base + __ffs(m1) - 1;
                    int pos = cnt1 + __popc(m1 & ltmask);
                    if ((d2 < R1SQ) && pos < K1_) o1[pos] = n;
                    cnt1 += __popc(m1); if (cnt1 > K1_) cnt1 = K1_;
                }
            }
            if (cnt0 < K0_) {
                unsigned m0 = __ballot_sync(0xffffffffu, d2 < R0SQ);
                if (m0) {
                    if (cnt0 == 0) first0 = base + __ffs(m0) - 1;
                    int pos = cnt0 + __popc(m0 & ltmask);
                    if ((d2 < R0SQ) && pos < K0_) o0[pos] = n;
                    cnt0 += __popc(m0); if (cnt0 > K0_) cnt0 = K0_;
                }
            } else if (cnt1 >= K1_) {
                break;
            }
        }
        for (int pos = cnt0 + lane; pos < K0_; pos += 32) o0[pos] = first0;
        for (int pos = cnt1 + lane; pos < K1_; pos += 32) o1[pos] = first1;
    }
}

// ---------------- layer-0 gather + BN stats ----------------
template <int K>
__global__ __launch_bounds__(256) void group2_kernel(
    const float* __restrict__ xyz, const float* __restrict__ newxyz,
    const float* __restrict__ Fp, const float* __restrict__ W /*64x67*/,
    const int* __restrict__ idx, float* __restrict__ Y, float* __restrict__ stats)
{
    constexpr int LK = (K == 16) ? 4 : 5;
    __shared__ float sms[64 * 132];
    __shared__ float swx[64], swy[64], swz[64];
    const int tid = threadIdx.x;
    const size_t m0 = (size_t)blockIdx.x * 128;

    if (tid < 64) {
        swx[tid] = W[tid * 67 + 0];
        swy[tid] = W[tid * 67 + 1];
        swz[tid] = W[tid * 67 + 2];
    }
    __syncthreads();

    {
        const int mloc = tid >> 1, half = tid & 1;
        const size_t m = m0 + mloc;
        const int n = idx[m];
        const int sflat = (int)(m >> LK);
        const int b = sflat >> 10;
        const float* ctr = newxyz + (size_t)sflat * 3;
        const float* p = xyz + ((size_t)(b << 12) + n) * 3;
        const float rx = p[0] - ctr[0], ry = p[1] - ctr[1], rz = p[2] - ctr[2];
        const float4* f = (const float4*)(Fp + (((size_t)(b << 12) + n) << 6) + half * 32);
        float* yrow = Y + m * 64 + half * 32;
#pragma unroll
        for (int cc = 0; cc < 8; ++cc) {
            float4 v = f[cc];
            int c = half * 32 + cc * 4;
            float4 o;
            o.x = fmaf(swx[c + 0], rx, fmaf(swy[c + 0], ry, fmaf(swz[c + 0], rz, v.x)));
            o.y = fmaf(swx[c + 1], rx, fmaf(swy[c + 1], ry, fmaf(swz[c + 1], rz, v.y)));
            o.z = fmaf(swx[c + 2], rx, fmaf(swy[c + 2], ry, fmaf(swz[c + 2], rz, v.z)));
            o.w = fmaf(swx[c + 3], rx, fmaf(swy[c + 3], ry, fmaf(swz[c + 3], rz, v.w)));
            sms[(c + 0) * 132 + mloc] = o.x;
            sms[(c + 1) * 132 + mloc] = o.y;
            sms[(c + 2) * 132 + mloc] = o.z;
            sms[(c + 3) * 132 + mloc] = o.w;
            *(float4*)(yrow + cc * 4) = o;
        }
    }
    __syncthreads();

    {
        const int c = tid >> 2, part = tid & 3;
        float s = 0.0f, s2 = 0.0f;
        const float4* row = (const float4*)(sms + c * 132 + part * 32);
#pragma unroll
        for (int q = 0; q < 8; ++q) {
            float4 v = row[q];
            s  += v.x + v.y + v.z + v.w;
            s2 += v.x * v.x + v.y * v.y + v.z * v.z + v.w * v.w;
        }
        s  += __shfl_down_sync(0xffffffffu, s, 2);
        s  += __shfl_down_sync(0xffffffffu, s, 1);
        s2 += __shfl_down_sync(0xffffffffu, s2, 2);
        s2 += __shfl_down_sync(0xffffffffu, s2, 1);
        if (part == 0) {
            atomicAdd(&stats[c], s);
            atomicAdd(&stats[128 + c], s2);
        }
    }
}

// ---------------- tf32 MMA GEMM (M-tile 256, warp = 64 rows x COUT/2) ----------------
template <int CIN, int COUT, int POOLK>
__global__ __launch_bounds__(256) void mma_kernel(
    const float* __restrict__ X, const float* __restrict__ W,
    float* __restrict__ Y, float* __restrict__ gmx, float* __restrict__ gmn,
    const float* __restrict__ affine, float* __restrict__ stats)
{
    constexpr int WCT = COUT / 16;     // n8-tiles per warp (COUT/2 per warp / 8)
    constexpr int XP = CIN + 4;
    constexpr int WP = COUT + 8;
    extern __shared__ float sm[];
    float* Wt  = sm;                   // [CIN][WP]
    float* Xs  = Wt + CIN * WP;        // [256][XP]
    float* red = Xs + 256 * XP;        // [2*COUT]
    const int tid = threadIdx.x;
    const size_t m0 = (size_t)blockIdx.x * 256;

    for (int i = tid; i < CIN * COUT; i += 256) {
        int co = i / CIN, k = i - co * CIN;
        Wt[k * WP + co] = f2tf_f(W[i]);
    }
    for (int i = tid; i < 256 * (CIN / 4); i += 256) {
        int row = i / (CIN / 4), c4 = i % (CIN / 4);
        int c = c4 * 4;
        float4 v = *(const float4*)(X + (m0 + row) * CIN + c);
        float4 o;
        o.x = f2tf_f(fmaxf(fmaf(v.x, affine[c + 0], affine[128 + c + 0]), 0.0f));
        o.y = f2tf_f(fmaxf(fmaf(v.y, affine[c + 1], affine[128 + c + 1]), 0.0f));
        o.z = f2tf_f(fmaxf(fmaf(v.z, affine[c + 2], affine[128 + c + 2]), 0.0f));
        o.w = f2tf_f(fmaxf(fmaf(v.w, affine[c + 3], affine[128 + c + 3]), 0.0f));
        *(float4*)(Xs + row * XP + c) = o;
    }
    if (tid < 2 * COUT) red[tid] = 0.0f;
    __syncthreads();

    const int lane = tid & 31, w = tid >> 5;
    const int gid = lane >> 2, tig = lane & 3;
    const int wm = (w & 3) * 64;                // 4 m-positions x 64 rows = 256
    const int wc = (w >> 2) * (COUT / 2);       // 2 co-halves

    float acc[4][WCT][4];
#pragma unroll
    for (int mt = 0; mt < 4; ++mt)
#pragma unroll
        for (int ct = 0; ct < WCT; ++ct)
#pragma unroll
            for (int r = 0; r < 4; ++r) acc[mt][ct][r] = 0.0f;

#pragma unroll
    for (int k0 = 0; k0 < CIN; k0 += 8) {
        uint32_t a[4][4];
#pragma unroll
        for (int mt = 0; mt < 4; ++mt) {
            int r = wm + mt * 16 + gid;
            a[mt][0] = __float_as_uint(Xs[r * XP + k0 + tig]);
            a[mt][1] = __float_as_uint(Xs[(r + 8) * XP + k0 + tig]);
            a[mt][2] = __float_as_uint(Xs[r * XP + k0 + tig + 4]);
            a[mt][3] = __float_as_uint(Xs[(r + 8) * XP + k0 + tig + 4]);
        }
        uint32_t bf[WCT][2];
#pragma unroll
        for (int ct = 0; ct < WCT; ++ct) {
            int co = wc + ct * 8 + gid;
            bf[ct][0] = __float_as_uint(Wt[(k0 + tig) * WP + co]);
            bf[ct][1] = __float_as_uint(Wt[(k0 + tig + 4) * WP + co]);
        }
#pragma unroll
        for (int mt = 0; mt < 4; ++mt)
#pragma unroll
            for (int ct = 0; ct < WCT; ++ct)
                mma_tf32(acc[mt][ct], a[mt], bf[ct]);
    }

    // ---- BN stats ----
#pragma unroll
    for (int ct = 0; ct < WCT; ++ct) {
        float se = 0, so = 0, qe = 0, qo = 0;
#pragma unroll
        for (int mt = 0; mt < 4; ++mt) {
            const float* d = acc[mt][ct];
            se += d[0] + d[2]; so += d[1] + d[3];
            qe += d[0] * d[0] + d[2] * d[2];
            qo += d[1] * d[1] + d[3] * d[3];
        }
#pragma unroll
        for (int off = 16; off >= 4; off >>= 1) {
            se += __shfl_down_sync(0xffffffffu, se, off);
            so += __shfl_down_sync(0xffffffffu, so, off);
            qe += __shfl_down_sync(0xffffffffu, qe, off);
            qo += __shfl_down_sync(0xffffffffu, qo, off);
        }
        if (gid == 0) {
            int co = wc + ct * 8 + tig * 2;
            atomicAdd(&red[co], se);
            atomicAdd(&red[co + 1], so);
            atomicAdd(&red[COUT + co], qe);
            atomicAdd(&red[COUT + co + 1], qo);
        }
    }

    if (POOLK == 0) {
#pragma unroll
        for (int mt = 0; mt < 4; ++mt)
#pragma unroll
            for (int ct = 0; ct < WCT; ++ct) {
                size_t m = m0 + wm + mt * 16 + gid;
                int co = wc + ct * 8 + tig * 2;
                const float* d = acc[mt][ct];
                *(float2*)(Y + m * COUT + co)       = make_float2(d[0], d[1]);
                *(float2*)(Y + (m + 8) * COUT + co) = make_float2(d[2], d[3]);
            }
    } else if (POOLK == 16) {
#pragma unroll
        for (int mt = 0; mt < 4; ++mt)
#pragma unroll
            for (int ct = 0; ct < WCT; ++ct) {
                const float* d = acc[mt][ct];
                float mxe = fmaxf(d[0], d[2]), mxo = fmaxf(d[1], d[3]);
                float mne = fminf(d[0], d[2]), mno = fminf(d[1], d[3]);
#pragma unroll
                for (int off = 16; off >= 4; off >>= 1) {
                    mxe = fmaxf(mxe, __shfl_down_sync(0xffffffffu, mxe, off));
                    mxo = fmaxf(mxo, __shfl_down_sync(0xffffffffu, mxo, off));
                    mne = fminf(mne, __shfl_down_sync(0xffffffffu, mne, off));
                    mno = fminf(mno, __shfl_down_sync(0xffffffffu, mno, off));
                }
                if (gid == 0) {
                    size_t g = (m0 + wm + mt * 16) >> 4;
                    int co = wc + ct * 8 + tig * 2;
                    *(float2*)(gmx + g * COUT + co) = make_float2(mxe, mxo);
                    *(float2*)(gmn + g * COUT + co) = make_float2(mne, mno);
                }
            }
    } else { // POOLK == 32: groups = mt-pairs
#pragma unroll
        for (int g2 = 0; g2 < 2; ++g2) {
#pragma unroll
            for (int ct = 0; ct < WCT; ++ct) {
                float mxe = -1e30f, mxo = -1e30f, mne = 1e30f, mno = 1e30f;
#pragma unroll
                for (int q = 0; q < 2; ++q) {
                    const float* d = acc[g2 * 2 + q][ct];
                    mxe = fmaxf(mxe, fmaxf(d[0], d[2]));
                    mxo = fmaxf(mxo, fmaxf(d[1], d[3]));
                    mne = fminf(mne, fminf(d[0], d[2]));
                    mno = fminf(mno, fminf(d[1], d[3]));
                }
#pragma unroll
                for (int off = 16; off >= 4; off >>= 1) {
                    mxe = fmaxf(mxe, __shfl_down_sync(0xffffffffu, mxe, off));
                    mxo = fmaxf(mxo, __shfl_down_sync(0xffffffffu, mxo, off));
                    mne = fminf(mne, __shfl_down_sync(0xffffffffu, mne, off));
                    mno = fminf(mno, __shfl_down_sync(0xffffffffu, mno, off));
                }
                if (gid == 0) {
                    size_t g = (m0 + wm + g2 * 32) >> 5;
                    int co = wc + ct * 8 + tig * 2;
                    *(float2*)(gmx + g * COUT + co) = make_float2(mxe, mxo);
                    *(float2*)(gmn + g * COUT + co) = make_float2(mne, mno);
                }
            }
        }
    }

    __syncthreads();
    if (tid < COUT) atomicAdd(&stats[tid], red[tid]);
    else if (tid < 2 * COUT) atomicAdd(&stats[128 + (tid - COUT)], red[tid]);
}

// ---------------- stats -> affine; zero stats ----------------
__global__ void affine_kernel(const float* __restrict__ g, const float* __restrict__ bt,
                              float* __restrict__ stats, float* __restrict__ affine,
                              int cout, float invM)
{
    int c = threadIdx.x;   // 128
    if (c < cout) {
        float mean = stats[c] * invM;
        float var  = stats[128 + c] * invM - mean * mean;
        float inv  = rsqrtf(var + EPS_);
        float a = g[c] * inv;
        affine[c] = a;
        affine[128 + c] = bt[c] - mean * a;
    }
    stats[c] = 0.0f;
    stats[128 + c] = 0.0f;
}

// ---------------- pooled affine+ReLU + transpose to (B,C,S) ----------------
__global__ __launch_bounds__(256) void pool2_kernel(
    const float* __restrict__ gmx, const float* __restrict__ gmn,
    float* __restrict__ outfeat, int cbase, const float* __restrict__ affine)
{
    __shared__ float st[128][33];
    const int b = blockIdx.y, s0 = blockIdx.x * 32;
    const int tid = threadIdx.x;
    {
        int c = tid & 127, sh = tid >> 7;
        float a = affine[c], bb = affine[128 + c];
#pragma unroll
        for (int j = 0; j < 16; ++j) {
            int s = s0 + sh * 16 + j;
            size_t g = ((size_t)(b << 10) + s) * 128 + c;
            float v = (a > 0.0f) ? gmx[g] : gmn[g];
            st[c][sh * 16 + j] = fmaxf(fmaf(a, v, bb), 0.0f);
        }
    }
    __syncthreads();
    {
        int c = tid >> 1, part = tid & 1;
        float* dst = outfeat + (((size_t)(b * 256 + cbase + c)) << 10) + s0 + part * 16;
#pragma unroll
        for (int j = 0; j < 4; ++j) {
            int s = part * 16 + j * 4;
            *(float4*)(dst + j * 4) = make_float4(st[c][s], st[c][s + 1], st[c][s + 2], st[c][s + 3]);
        }
    }
}

// ---------------- host launch ----------------
extern "C" void kernel_launch(void* const* d_in, const int* in_sizes, int n_in,
                              void* d_out, int out_size)
{
    const float* xyz  = (const float*)d_in[0];
    const float* feat = (const float*)d_in[1];
    const float* w0[3] = { (const float*)d_in[2], (const float*)d_in[5], (const float*)d_in[8] };
    const float* g0[3] = { (const float*)d_in[3], (const float*)d_in[6], (const float*)d_in[9] };
    const float* b0[3] = { (const float*)d_in[4], (const float*)d_in[7], (const float*)d_in[10] };
    const float* w1[3] = { (const float*)d_in[11], (const float*)d_in[14], (const float*)d_in[17] };
    const float* g1[3] = { (const float*)d_in[12], (const float*)d_in[15], (const float*)d_in[18] };
    const float* b1[3] = { (const float*)d_in[13], (const float*)d_in[16], (const float*)d_in[19] };

    float* out = (float*)d_out;
    float* newxyz = out;
    float* outfeat = out + (size_t)B_ * S_ * 3;

    float *a0, *b0buf, *a1, *b1buf, *fp0, *fp1;
    float *gmx0, *gmn0, *gmx1, *gmn1, *st0, *af0, *st1, *af1;
    int *idx0, *idx1;
    cudaGetSymbolAddress((void**)&a0, g_a0);
    cudaGetSymbolAddress((void**)&b0buf, g_b0);
    cudaGetSymbolAddress((void**)&a1, g_a1);
    cudaGetSymbolAddress((void**)&b1buf, g_b1);
    cudaGetSymbolAddress((void**)&fp0, g_fp0);
    cudaGetSymbolAddress((void**)&fp1, g_fp1);
    cudaGetSymbolAddress((void**)&gmx0, g_gmx0);
    cudaGetSymbolAddress((void**)&gmn0, g_gmn0);
    cudaGetSymbolAddress((void**)&gmx1, g_gmx1);
    cudaGetSymbolAddress((void**)&gmn1, g_gmn1);
    cudaGetSymbolAddress((void**)&st0, g_stats0);
    cudaGetSymbolAddress((void**)&af0, g_affine0);
    cudaGetSymbolAddress((void**)&st1, g_stats1);
    cudaGetSymbolAddress((void**)&af1, g_affine1);
    cudaGetSymbolAddress((void**)&idx0, g_idx0);
    cudaGetSymbolAddress((void**)&idx1, g_idx1);

    auto shb = [](int cin, int cout) { return (cin * (cout + 8) + 256 * (cin + 4) + 2 * cout) * 4; };
    const int fps_smem = 3 * N_ * 4;
    const int fg_smem = (64 * 65 + 64 * 128) * 4;

    static cudaStream_t sB = nullptr, sC = nullptr;
    static cudaEvent_t eRoot = nullptr, eFG = nullptr, eBQ = nullptr, eS1 = nullptr;
    if (!sB) {
        cudaStreamCreateWithFlags(&sB, cudaStreamNonBlocking);
        cudaStreamCreateWithFlags(&sC, cudaStreamNonBlocking);
        cudaEventCreateWithFlags(&eRoot, cudaEventDisableTiming);
        cudaEventCreateWithFlags(&eFG, cudaEventDisableTiming);
        cudaEventCreateWithFlags(&eBQ, cudaEventDisableTiming);
        cudaEventCreateWithFlags(&eS1, cudaEventDisableTiming);
        cudaFuncSetAttribute(mma_kernel<64, 64, 0>,   cudaFuncAttributeMaxDynamicSharedMemorySize, shb(64, 64));
        cudaFuncSetAttribute(mma_kernel<64, 96, 0>,   cudaFuncAttributeMaxDynamicSharedMemorySize, shb(64, 96));
        cudaFuncSetAttribute(mma_kernel<64, 128, 16>, cudaFuncAttributeMaxDynamicSharedMemorySize, shb(64, 128));
        cudaFuncSetAttribute(mma_kernel<96, 128, 32>, cudaFuncAttributeMaxDynamicSharedMemorySize, shb(96, 128));
        cudaFuncSetAttribute(featgemm2_kernel,        cudaFuncAttributeMaxDynamicSharedMemorySize, fg_smem);
        cudaFuncSetAttribute(fps_kernel,              cudaFuncAttributeMaxDynamicSharedMemorySize, fps_smem);
    }

    // ---- capture fork: root event on the capture-origin stream ----
    cudaEventRecord(eRoot, 0);
    cudaStreamWaitEvent(sB, eRoot, 0);
    cudaStreamWaitEvent(sC, eRoot, 0);

    // stream B: feature pre-GEMM (independent of FPS)
    featgemm2_kernel<<<dim3(N_ / 128, B_), 256, fg_smem, sB>>>(feat, w0[0], w1[0], fp0, fp1);
    cudaEventRecord(eFG, sB);

    // stream 0: FPS -> ballquery
    fps_kernel<<<B_, 1024, fps_smem>>>(xyz, newxyz);
    ballquery_kernel<<<dim3(S_ / 64, B_), 512>>>(xyz, newxyz, idx0, idx1);
    cudaEventRecord(eBQ, 0);

    // stream C: scale-1 chain
    cudaStreamWaitEvent(sC, eBQ, 0);
    cudaStreamWaitEvent(sC, eFG, 0);
    group2_kernel<K1_><<<M1_ / 128, 256, 0, sC>>>(xyz, newxyz, fp1, w1[0], idx1, a1, st1);
    affine_kernel<<<1, 128, 0, sC>>>(g1[0], b1[0], st1, af1, 64, 1.0f / M1_);
    mma_kernel<64, 96, 0><<<M1_ / 256, 256, shb(64, 96), sC>>>(a1, w1[1], b1buf, nullptr, nullptr, af1, st1);
    affine_kernel<<<1, 128, 0, sC>>>(g1[1], b1[1], st1, af1, 96, 1.0f / M1_);
    mma_kernel<96, 128, 32><<<M1_ / 256, 256, shb(96, 128), sC>>>(b1buf, w1[2], nullptr, gmx1, gmn1, af1, st1);
    affine_kernel<<<1, 128, 0, sC>>>(g1[2], b1[2], st1, af1, 128, 1.0f / M1_);
    pool2_kernel<<<dim3(S_ / 32, B_), 256, 0, sC>>>(gmx1, gmn1, outfeat, 128, af1);
    cudaEventRecord(eS1, sC);

    // stream 0: scale-0 chain
    cudaStreamWaitEvent(0, eFG, 0);
    group2_kernel<K0_><<<M0_ / 128, 256>>>(xyz, newxyz, fp0, w0[0], idx0, a0, st0);
    affine_kernel<<<1, 128>>>(g0[0], b0[0], st0, af0, 64, 1.0f / M0_);
    mma_kernel<64, 64, 0><<<M0_ / 256, 256, shb(64, 64)>>>(a0, w0[1], b0buf, nullptr, nullptr, af0, st0);
    affine_kernel<<<1, 128>>>(g0[1], b0[1], st0, af0, 64, 1.0f / M0_);
    mma_kernel<64, 128, 16><<<M0_ / 256, 256, shb(64, 128)>>>(b0buf, w0[2], nullptr, gmx0, gmn0, af0, st0);
    affine_kernel<<<1, 128>>>(g0[2], b0[2], st0, af0, 128, 1.0f / M0_);
    pool2_kernel<<<dim3(S_ / 32, B_), 256>>>(gmx0, gmn0, outfeat, 0, af0);

    // join side stream back into the capture-origin stream
    cudaStreamWaitEvent(0, eS1, 0);
}

// round 10
// speedup vs baseline: 1.1536x; 1.1536x over previous
#include <cuda_runtime.h>
#include <cuda_fp16.h>
#include <cstdint>

#define B_   16
#define N_   4096
#define C_   64
#define S_   1024
#define K0_  16
#define K1_  32
#define M0_  (B_ * S_ * K0_)   // 262144
#define M1_  (B_ * S_ * K1_)   // 524288
#define R0SQ 0.01f
#define R1SQ 0.04f
#define EPS_ 1e-5f

// ---------------- scratch (device globals, zero-init) ----------------
__device__ __half g_fp0[B_ * N_ * C_];     // F' scale 0, fp16
__device__ __half g_fp1[B_ * N_ * C_];     // F' scale 1, fp16
__device__ int    g_idx0[B_ * S_ * K0_];
__device__ int    g_idx1[B_ * S_ * K1_];
__device__ __half g_a0[64u * 262144u];     // s0 layer0 out
__device__ __half g_b0[64u * 262144u];     // s0 layer1 out
__device__ __half g_a1[64u * 524288u];     // s1 layer0 out
__device__ __half g_b1[96u * 524288u];     // s1 layer1 out
__device__ float  g_gmx0[16384u * 128u];
__device__ float  g_gmn0[16384u * 128u];
__device__ float  g_gmx1[16384u * 128u];
__device__ float  g_gmn1[16384u * 128u];
__device__ float  g_stats0[256];
__device__ float  g_affine0[256];
__device__ float  g_stats1[256];
__device__ float  g_affine1[256];

__device__ __forceinline__ float f2tf_f(float x) {
    uint32_t r;
    asm("cvt.rna.tf32.f32 %0, %1;" : "=r"(r) : "f"(x));
    return __uint_as_float(r);
}

__device__ __forceinline__ void mma_tf32(float* d, const uint32_t* a, const uint32_t* b) {
    asm volatile("mma.sync.aligned.m16n8k8.row.col.f32.tf32.tf32.f32 "
                 "{%0,%1,%2,%3}, {%4,%5,%6,%7}, {%8,%9}, {%0,%1,%2,%3};"
                 : "+f"(d[0]), "+f"(d[1]), "+f"(d[2]), "+f"(d[3])
                 : "r"(a[0]), "r"(a[1]), "r"(a[2]), "r"(a[3]), "r"(b[0]), "r"(b[1]));
}

// ---------------- FPS (redux-based reduction) ----------------
__global__ void fps_kernel(const float* __restrict__ xyz, float* __restrict__ newxyz)
{
    extern __shared__ float sm[];
    float* sx = sm; float* sy = sm + N_; float* sz = sm + 2 * N_;
    __shared__ unsigned sbits[2][32];
    __shared__ int      sidx[2][32];

    const int b = blockIdx.x;
    const int t = threadIdx.x;          // 1024
    const int lane = t & 31, wid = t >> 5;

    for (int i = t; i < N_; i += 1024) {
        const float* p = xyz + ((size_t)b * N_ + i) * 3;
        sx[i] = p[0]; sy[i] = p[1]; sz[i] = p[2];
    }
    __syncthreads();

    float px[4], py[4], pz[4], dist[4];
#pragma unroll
    for (int j = 0; j < 4; ++j) {
        int n = t + (j << 10);
        px[j] = sx[n]; py[j] = sy[n]; pz[j] = sz[n];
        dist[j] = 1e10f;
    }

    if (t == 0) {
        float* o = newxyz + (size_t)b * S_ * 3;
        o[0] = sx[0]; o[1] = sy[0]; o[2] = sz[0];
    }
    float lx = sx[0], ly = sy[0], lz = sz[0];

    int p_ = 0;
    for (int i = 1; i < S_; ++i) {
        float bv = -1.0f; int bi = 0;
#pragma unroll
        for (int j = 0; j < 4; ++j) {
            float dx = px[j] - lx, dy = py[j] - ly, dz = pz[j] - lz;
            float d = dx * dx + dy * dy + dz * dz;
            float nd = fminf(dist[j], d);
            dist[j] = nd;
            if (nd > bv) { bv = nd; bi = t + (j << 10); }
        }
        unsigned dbits = __float_as_uint(bv);
        unsigned wmax = __reduce_max_sync(0xffffffffu, dbits);
        unsigned cand = (dbits == wmax) ? (unsigned)bi : 0xffffffffu;
        unsigned widx = __reduce_min_sync(0xffffffffu, cand);
        if (lane == 0) { sbits[p_][wid] = wmax; sidx[p_][wid] = (int)widx; }
        __syncthreads();
        unsigned vb = sbits[p_][lane];
        int      vi = sidx[p_][lane];
        unsigned bmax = __reduce_max_sync(0xffffffffu, vb);
        unsigned c2 = (vb == bmax) ? (unsigned)vi : 0xffffffffu;
        int bsel = (int)__reduce_min_sync(0xffffffffu, c2);
        lx = sx[bsel]; ly = sy[bsel]; lz = sz[bsel];
        if (t == 0) {
            float* o = newxyz + ((size_t)b * S_ + i) * 3;
            o[0] = lx; o[1] = ly; o[2] = lz;
        }
        p_ ^= 1;
    }
}

// ---------------- combined feature pre-GEMM -> fp16 F' ----------------
__global__ __launch_bounds__(256) void featgemm2_kernel(
    const float* __restrict__ feat,
    const float* __restrict__ W0, const float* __restrict__ W1,
    __half* __restrict__ Fp0, __half* __restrict__ Fp1)
{
    extern __shared__ float sm[];
    float* Wt = sm;             // [64][65]
    float* Xs = Wt + 64 * 65;   // [64][128]
    const int tid = threadIdx.x;
    const int b = blockIdx.y;
    const int n0 = blockIdx.x * 128;

    for (int i = tid; i < 64 * 32; i += 256) {
        int k = i >> 5, q = i & 31;
        *(float4*)(Xs + k * 128 + q * 4) =
            *(const float4*)(feat + ((size_t)(b * 64 + k)) * N_ + n0 + q * 4);
    }

    const int mi = tid & 15, ci = tid >> 4;
#pragma unroll
    for (int s = 0; s < 2; ++s) {
        const float* W = s ? W1 : W0;
        __half* Fp = s ? Fp1 : Fp0;
        __syncthreads();
        for (int i = tid; i < 64 * 64; i += 256) {
            int co = i >> 6, k = i & 63;
            Wt[k * 65 + co] = W[co * 67 + 3 + k];
        }
        __syncthreads();

        float acc[4][8];
#pragma unroll
        for (int j = 0; j < 4; ++j)
#pragma unroll
            for (int r = 0; r < 8; ++r) acc[j][r] = 0.0f;

#pragma unroll 4
        for (int k = 0; k < 64; ++k) {
            float xf[8];
            *(float4*)xf       = *(const float4*)(Xs + k * 128 + mi * 8);
            *(float4*)(xf + 4) = *(const float4*)(Xs + k * 128 + mi * 8 + 4);
#pragma unroll
            for (int j = 0; j < 4; ++j) {
                float w = Wt[k * 65 + ci * 4 + j];
#pragma unroll
                for (int r = 0; r < 8; ++r) acc[j][r] = fmaf(w, xf[r], acc[j][r]);
            }
        }
#pragma unroll
        for (int r = 0; r < 8; ++r) {
            size_t row = (size_t)(b << 12) + n0 + mi * 8 + r;
            __half2 h0 = __floats2half2_rn(acc[0][r], acc[1][r]);
            __half2 h1 = __floats2half2_rn(acc[2][r], acc[3][r]);
            uint2 u = make_uint2(*(uint32_t*)&h0, *(uint32_t*)&h1);
            *(uint2*)(Fp + (row << 6) + ci * 4) = u;
        }
    }
}

// ---------------- fused ball query (conditional ballots) ----------------
__global__ void ballquery_kernel(const float* __restrict__ xyz,
                                 const float* __restrict__ newxyz,
                                 int* __restrict__ idx0, int* __restrict__ idx1)
{
    __shared__ float sx[N_], sy[N_], sz[N_];
    const int bb = blockIdx.y;
    const int tid = threadIdx.x;                 // 512
    const int lane = tid & 31, w = tid >> 5;

    for (int i = tid; i < N_ * 3; i += 512) {
        float v = xyz[(size_t)bb * N_ * 3 + i];
        int n = i / 3, d = i - n * 3;
        if (d == 0) sx[n] = v; else if (d == 1) sy[n] = v; else sz[n] = v;
    }
    __syncthreads();

    const unsigned ltmask = (1u << lane) - 1u;

    for (int cc = 0; cc < 4; ++cc) {
        int s_ = blockIdx.x * 64 + w * 4 + cc;
        const float* ctr = newxyz + ((size_t)bb * S_ + s_) * 3;
        float cx = ctr[0], cy = ctr[1], cz = ctr[2];
        int* o0 = idx0 + ((size_t)bb * S_ + s_) * K0_;
        int* o1 = idx1 + ((size_t)bb * S_ + s_) * K1_;
        int cnt0 = 0, cnt1 = 0, first0 = 0, first1 = 0;

        for (int base = 0; base < N_; base += 32) {
            int n = base + lane;
            float dx = sx[n] - cx, dy = sy[n] - cy, dz = sz[n] - cz;
            float d2 = dx * dx + dy * dy + dz * dz;
            if (cnt1 < K1_) {
                unsigned m1 = __ballot_sync(0xffffffffu, d2 < R1SQ);
                if (m1) {
                    if (cnt1 == 0) first1 = base + __ffs(m1) - 1;
                    int pos = cnt1 + __popc(m1 & ltmask);
                    if ((d2 < R1SQ) && pos < K1_) o1[pos] = n;
                    cnt1 += __popc(m1); if (cnt1 > K1_) cnt1 = K1_;
                }
            }
            if (cnt0 < K0_) {
                unsigned m0 = __ballot_sync(0xffffffffu, d2 < R0SQ);
                if (m0) {
                    if (cnt0 == 0) first0 = base + __ffs(m0) - 1;
                    int pos = cnt0 + __popc(m0 & ltmask);
                    if ((d2 < R0SQ) && pos < K0_) o0[pos] = n;
                    cnt0 += __popc(m0); if (cnt0 > K0_) cnt0 = K0_;
                }
            } else if (cnt1 >= K1_) {
                break;
            }
        }
        for (int pos = cnt0 + lane; pos < K0_; pos += 32) o0[pos] = first0;
        for (int pos = cnt1 + lane; pos < K1_; pos += 32) o1[pos] = first1;
    }
}

// ---------------- layer-0 gather (fp16 F' in, fp16 Y out) + fp32 BN stats ----------------
template <int K>
__global__ __launch_bounds__(256) void group2_kernel(
    const float* __restrict__ xyz, const float* __restrict__ newxyz,
    const __half* __restrict__ Fp, const float* __restrict__ W /*64x67*/,
    const int* __restrict__ idx, __half* __restrict__ Y, float* __restrict__ stats)
{
    constexpr int LK = (K == 16) ? 4 : 5;
    __shared__ float sms[64 * 132];
    __shared__ float swx[64], swy[64], swz[64];
    const int tid = threadIdx.x;
    const size_t m0 = (size_t)blockIdx.x * 128;

    if (tid < 64) {
        swx[tid] = W[tid * 67 + 0];
        swy[tid] = W[tid * 67 + 1];
        swz[tid] = W[tid * 67 + 2];
    }
    __syncthreads();

    {
        const int mloc = tid >> 1, half = tid & 1;
        const size_t m = m0 + mloc;
        const int n = idx[m];
        const int sflat = (int)(m >> LK);
        const int b = sflat >> 10;
        const float* ctr = newxyz + (size_t)sflat * 3;
        const float* p = xyz + ((size_t)(b << 12) + n) * 3;
        const float rx = p[0] - ctr[0], ry = p[1] - ctr[1], rz = p[2] - ctr[2];
        const uint2* f = (const uint2*)(Fp + (((size_t)(b << 12) + n) << 6) + half * 32);
        __half* yrow = Y + m * 64 + half * 32;
#pragma unroll
        for (int cc = 0; cc < 8; ++cc) {
            uint2 u = f[cc];
            __half2 hv0 = *(__half2*)&u.x;
            __half2 hv1 = *(__half2*)&u.y;
            int c = half * 32 + cc * 4;
            float4 o;
            o.x = fmaf(swx[c + 0], rx, fmaf(swy[c + 0], ry, fmaf(swz[c + 0], rz, __low2float(hv0))));
            o.y = fmaf(swx[c + 1], rx, fmaf(swy[c + 1], ry, fmaf(swz[c + 1], rz, __high2float(hv0))));
            o.z = fmaf(swx[c + 2], rx, fmaf(swy[c + 2], ry, fmaf(swz[c + 2], rz, __low2float(hv1))));
            o.w = fmaf(swx[c + 3], rx, fmaf(swy[c + 3], ry, fmaf(swz[c + 3], rz, __high2float(hv1))));
            sms[(c + 0) * 132 + mloc] = o.x;
            sms[(c + 1) * 132 + mloc] = o.y;
            sms[(c + 2) * 132 + mloc] = o.z;
            sms[(c + 3) * 132 + mloc] = o.w;
            __half2 w0 = __floats2half2_rn(o.x, o.y);
            __half2 w1 = __floats2half2_rn(o.z, o.w);
            *(uint2*)(yrow + cc * 4) = make_uint2(*(uint32_t*)&w0, *(uint32_t*)&w1);
        }
    }
    __syncthreads();

    {
        const int c = tid >> 2, part = tid & 3;
        float s = 0.0f, s2 = 0.0f;
        const float4* row = (const float4*)(sms + c * 132 + part * 32);
#pragma unroll
        for (int q = 0; q < 8; ++q) {
            float4 v = row[q];
            s  += v.x + v.y + v.z + v.w;
            s2 += v.x * v.x + v.y * v.y + v.z * v.z + v.w * v.w;
        }
        s  += __shfl_down_sync(0xffffffffu, s, 2);
        s  += __shfl_down_sync(0xffffffffu, s, 1);
        s2 += __shfl_down_sync(0xffffffffu, s2, 2);
        s2 += __shfl_down_sync(0xffffffffu, s2, 1);
        if (part == 0) {
            atomicAdd(&stats[c], s);
            atomicAdd(&stats[128 + c], s2);
        }
    }
}

// ---------------- tf32 MMA GEMM (M=128, mt=2), fp16 in/out streams ----------------
template <int CIN, int COUT, int POOLK>
__global__ __launch_bounds__(256) void mma_kernel(
    const __half* __restrict__ X, const float* __restrict__ W,
    __half* __restrict__ Y, float* __restrict__ gmx, float* __restrict__ gmn,
    const float* __restrict__ affine, float* __restrict__ stats)
{
    constexpr int WCT = COUT / 16;
    constexpr int XP = CIN + 4;
    constexpr int WP = COUT + 8;
    extern __shared__ float sm[];
    float* Wt  = sm;                   // [CIN][WP]
    float* Xs  = Wt + CIN * WP;        // [128][XP]
    float* red = Xs + 128 * XP;        // [2*COUT]
    const int tid = threadIdx.x;
    const size_t m0 = (size_t)blockIdx.x * 128;

    for (int i = tid; i < CIN * COUT; i += 256) {
        int co = i / CIN, k = i - co * CIN;
        Wt[k * WP + co] = f2tf_f(W[i]);
    }
    for (int i = tid; i < 128 * (CIN / 4); i += 256) {
        int row = i / (CIN / 4), c4 = i % (CIN / 4);
        int c = c4 * 4;
        uint2 u = *(const uint2*)(X + (m0 + row) * CIN + c);
        __half2 h0 = *(__half2*)&u.x;
        __half2 h1 = *(__half2*)&u.y;
        float4 o;
        o.x = f2tf_f(fmaxf(fmaf(__low2float(h0),  affine[c + 0], affine[128 + c + 0]), 0.0f));
        o.y = f2tf_f(fmaxf(fmaf(__high2float(h0), affine[c + 1], affine[128 + c + 1]), 0.0f));
        o.z = f2tf_f(fmaxf(fmaf(__low2float(h1),  affine[c + 2], affine[128 + c + 2]), 0.0f));
        o.w = f2tf_f(fmaxf(fmaf(__high2float(h1), affine[c + 3], affine[128 + c + 3]), 0.0f));
        *(float4*)(Xs + row * XP + c) = o;
    }
    if (tid < 2 * COUT) red[tid] = 0.0f;
    __syncthreads();

    const int lane = tid & 31, w = tid >> 5;
    const int gid = lane >> 2, tig = lane & 3;
    const int wm = (w & 3) * 32;
    const int wc = (w >> 2) * (COUT / 2);

    float acc[2][WCT][4];
#pragma unroll
    for (int mt = 0; mt < 2; ++mt)
#pragma unroll
        for (int ct = 0; ct < WCT; ++ct)
#pragma unroll
            for (int r = 0; r < 4; ++r) acc[mt][ct][r] = 0.0f;

#pragma unroll
    for (int k0 = 0; k0 < CIN; k0 += 8) {
        uint32_t a[2][4];
#pragma unroll
        for (int mt = 0; mt < 2; ++mt) {
            int r = wm + mt * 16 + gid;
            a[mt][0] = __float_as_uint(Xs[r * XP + k0 + tig]);
            a[mt][1] = __float_as_uint(Xs[(r + 8) * XP + k0 + tig]);
            a[mt][2] = __float_as_uint(Xs[r * XP + k0 + tig + 4]);
            a[mt][3] = __float_as_uint(Xs[(r + 8) * XP + k0 + tig + 4]);
        }
        uint32_t bf[WCT][2];
#pragma unroll
        for (int ct = 0; ct < WCT; ++ct) {
            int co = wc + ct * 8 + gid;
            bf[ct][0] = __float_as_uint(Wt[(k0 + tig) * WP + co]);
            bf[ct][1] = __float_as_uint(Wt[(k0 + tig + 4) * WP + co]);
        }
#pragma unroll
        for (int mt = 0; mt < 2; ++mt)
#pragma unroll
            for (int ct = 0; ct < WCT; ++ct)
                mma_tf32(acc[mt][ct], a[mt], bf[ct]);
    }

#pragma unroll
    for (int ct = 0; ct < WCT; ++ct) {
        float se = 0, so = 0, qe = 0, qo = 0;
#pragma unroll
        for (int mt = 0; mt < 2; ++mt) {
            const float* d = acc[mt][ct];
            se += d[0] + d[2]; so += d[1] + d[3];
            qe += d[0] * d[0] + d[2] * d[2];
            qo += d[1] * d[1] + d[3] * d[3];
        }
#pragma unroll
        for (int off = 16; off >= 4; off >>= 1) {
            se += __shfl_down_sync(0xffffffffu, se, off);
            so += __shfl_down_sync(0xffffffffu, so, off);
            qe += __shfl_down_sync(0xffffffffu, qe, off);
            qo += __shfl_down_sync(0xffffffffu, qo, off);
        }
        if (gid == 0) {
            int co = wc + ct * 8 + tig * 2;
            atomicAdd(&red[co], se);
            atomicAdd(&red[co + 1], so);
            atomicAdd(&red[COUT + co], qe);
            atomicAdd(&red[COUT + co + 1], qo);
        }
    }

    if (POOLK == 0) {
#pragma unroll
        for (int mt = 0; mt < 2; ++mt)
#pragma unroll
            for (int ct = 0; ct < WCT; ++ct) {
                size_t m = m0 + wm + mt * 16 + gid;
                int co = wc + ct * 8 + tig * 2;
                const float* d = acc[mt][ct];
                __half2 h0 = __floats2half2_rn(d[0], d[1]);
                __half2 h1 = __floats2half2_rn(d[2], d[3]);
                *(__half2*)(Y + m * COUT + co)       = h0;
                *(__half2*)(Y + (m + 8) * COUT + co) = h1;
            }
    } else if (POOLK == 16) {
#pragma unroll
        for (int mt = 0; mt < 2; ++mt)
#pragma unroll
            for (int ct = 0; ct < WCT; ++ct) {
                const float* d = acc[mt][ct];
                float mxe = fmaxf(d[0], d[2]), mxo = fmaxf(d[1], d[3]);
                float mne = fminf(d[0], d[2]), mno = fminf(d[1], d[3]);
#pragma unroll
                for (int off = 16; off >= 4; off >>= 1) {
                    mxe = fmaxf(mxe, __shfl_down_sync(0xffffffffu, mxe, off));
                    mxo = fmaxf(mxo, __shfl_down_sync(0xffffffffu, mxo, off));
                    mne = fminf(mne, __shfl_down_sync(0xffffffffu, mne, off));
                    mno = fminf(mno, __shfl_down_sync(0xffffffffu, mno, off));
                }
                if (gid == 0) {
                    size_t g = (m0 + wm + mt * 16) >> 4;
                    int co = wc + ct * 8 + tig * 2;
                    *(float2*)(gmx + g * COUT + co) = make_float2(mxe, mxo);
                    *(float2*)(gmn + g * COUT + co) = make_float2(mne, mno);
                }
            }
    } else { // POOLK == 32
#pragma unroll
        for (int ct = 0; ct < WCT; ++ct) {
            float mxe = -1e30f, mxo = -1e30f, mne = 1e30f, mno = 1e30f;
#pragma unroll
            for (int mt = 0; mt < 2; ++mt) {
                const float* d = acc[mt][ct];
                mxe = fmaxf(mxe, fmaxf(d[0], d[2]));
                mxo = fmaxf(mxo, fmaxf(d[1], d[3]));
                mne = fminf(mne, fminf(d[0], d[2]));
                mno = fminf(mno, fminf(d[1], d[3]));
            }
#pragma unroll
            for (int off = 16; off >= 4; off >>= 1) {
                mxe = fmaxf(mxe, __shfl_down_sync(0xffffffffu, mxe, off));
                mxo = fmaxf(mxo, __shfl_down_sync(0xffffffffu, mxo, off));
                mne = fminf(mne, __shfl_down_sync(0xffffffffu, mne, off));
                mno = fminf(mno, __shfl_down_sync(0xffffffffu, mno, off));
            }
            if (gid == 0) {
                size_t g = (m0 + wm) >> 5;
                int co = wc + ct * 8 + tig * 2;
                *(float2*)(gmx + g * COUT + co) = make_float2(mxe, mxo);
                *(float2*)(gmn + g * COUT + co) = make_float2(mne, mno);
            }
        }
    }

    __syncthreads();
    if (tid < COUT) atomicAdd(&stats[tid], red[tid]);
    else if (tid < 2 * COUT) atomicAdd(&stats[128 + (tid - COUT)], red[tid]);
}

// ---------------- stats -> affine; zero stats ----------------
__global__ void affine_kernel(const float* __restrict__ g, const float* __restrict__ bt,
                              float* __restrict__ stats, float* __restrict__ affine,
                              int cout, float invM)
{
    int c = threadIdx.x;   // 128
    if (c < cout) {
        float mean = stats[c] * invM;
        float var  = stats[128 + c] * invM - mean * mean;
        float inv  = rsqrtf(var + EPS_);
        float a = g[c] * inv;
        affine[c] = a;
        affine[128 + c] = bt[c] - mean * a;
    }
    stats[c] = 0.0f;
    stats[128 + c] = 0.0f;
}

// ---------------- pooled affine+ReLU + transpose to (B,C,S) ----------------
__global__ __launch_bounds__(256) void pool2_kernel(
    const float* __restrict__ gmx, const float* __restrict__ gmn,
    float* __restrict__ outfeat, int cbase, const float* __restrict__ affine)
{
    __shared__ float st[128][33];
    const int b = blockIdx.y, s0 = blockIdx.x * 32;
    const int tid = threadIdx.x;
    {
        int c = tid & 127, sh = tid >> 7;
        float a = affine[c], bb = affine[128 + c];
#pragma unroll
        for (int j = 0; j < 16; ++j) {
            int s = s0 + sh * 16 + j;
            size_t g = ((size_t)(b << 10) + s) * 128 + c;
            float v = (a > 0.0f) ? gmx[g] : gmn[g];
            st[c][sh * 16 + j] = fmaxf(fmaf(a, v, bb), 0.0f);
        }
    }
    __syncthreads();
    {
        int c = tid >> 1, part = tid & 1;
        float* dst = outfeat + (((size_t)(b * 256 + cbase + c)) << 10) + s0 + part * 16;
#pragma unroll
        for (int j = 0; j < 4; ++j) {
            int s = part * 16 + j * 4;
            *(float4*)(dst + j * 4) = make_float4(st[c][s], st[c][s + 1], st[c][s + 2], st[c][s + 3]);
        }
    }
}

// ---------------- host launch ----------------
extern "C" void kernel_launch(void* const* d_in, const int* in_sizes, int n_in,
                              void* d_out, int out_size)
{
    const float* xyz  = (const float*)d_in[0];
    const float* feat = (const float*)d_in[1];
    const float* w0[3] = { (const float*)d_in[2], (const float*)d_in[5], (const float*)d_in[8] };
    const float* g0[3] = { (const float*)d_in[3], (const float*)d_in[6], (const float*)d_in[9] };
    const float* b0[3] = { (const float*)d_in[4], (const float*)d_in[7], (const float*)d_in[10] };
    const float* w1[3] = { (const float*)d_in[11], (const float*)d_in[14], (const float*)d_in[17] };
    const float* g1[3] = { (const float*)d_in[12], (const float*)d_in[15], (const float*)d_in[18] };
    const float* b1[3] = { (const float*)d_in[13], (const float*)d_in[16], (const float*)d_in[19] };

    float* out = (float*)d_out;
    float* newxyz = out;
    float* outfeat = out + (size_t)B_ * S_ * 3;

    __half *a0, *b0buf, *a1, *b1buf, *fp0, *fp1;
    float *gmx0, *gmn0, *gmx1, *gmn1, *st0, *af0, *st1, *af1;
    int *idx0, *idx1;
    cudaGetSymbolAddress((void**)&a0, g_a0);
    cudaGetSymbolAddress((void**)&b0buf, g_b0);
    cudaGetSymbolAddress((void**)&a1, g_a1);
    cudaGetSymbolAddress((void**)&b1buf, g_b1);
    cudaGetSymbolAddress((void**)&fp0, g_fp0);
    cudaGetSymbolAddress((void**)&fp1, g_fp1);
    cudaGetSymbolAddress((void**)&gmx0, g_gmx0);
    cudaGetSymbolAddress((void**)&gmn0, g_gmn0);
    cudaGetSymbolAddress((void**)&gmx1, g_gmx1);
    cudaGetSymbolAddress((void**)&gmn1, g_gmn1);
    cudaGetSymbolAddress((void**)&st0, g_stats0);
    cudaGetSymbolAddress((void**)&af0, g_affine0);
    cudaGetSymbolAddress((void**)&st1, g_stats1);
    cudaGetSymbolAddress((void**)&af1, g_affine1);
    cudaGetSymbolAddress((void**)&idx0, g_idx0);
    cudaGetSymbolAddress((void**)&idx1, g_idx1);

    auto shb = [](int cin, int cout) { return (cin * (cout + 8) + 128 * (cin + 4) + 2 * cout) * 4; };
    const int fps_smem = 3 * N_ * 4;
    const int fg_smem = (64 * 65 + 64 * 128) * 4;

    static cudaStream_t sB = nullptr, sC = nullptr;
    static cudaEvent_t eRoot = nullptr, eFG = nullptr, eBQ = nullptr, eS1 = nullptr;
    if (!sB) {
        cudaStreamCreateWithFlags(&sB, cudaStreamNonBlocking);
        cudaStreamCreateWithFlags(&sC, cudaStreamNonBlocking);
        cudaEventCreateWithFlags(&eRoot, cudaEventDisableTiming);
        cudaEventCreateWithFlags(&eFG, cudaEventDisableTiming);
        cudaEventCreateWithFlags(&eBQ, cudaEventDisableTiming);
        cudaEventCreateWithFlags(&eS1, cudaEventDisableTiming);
        cudaFuncSetAttribute(mma_kernel<64, 64, 0>,   cudaFuncAttributeMaxDynamicSharedMemorySize, shb(64, 64));
        cudaFuncSetAttribute(mma_kernel<64, 96, 0>,   cudaFuncAttributeMaxDynamicSharedMemorySize, shb(64, 96));
        cudaFuncSetAttribute(mma_kernel<64, 128, 16>, cudaFuncAttributeMaxDynamicSharedMemorySize, shb(64, 128));
        cudaFuncSetAttribute(mma_kernel<96, 128, 32>, cudaFuncAttributeMaxDynamicSharedMemorySize, shb(96, 128));
        cudaFuncSetAttribute(featgemm2_kernel,        cudaFuncAttributeMaxDynamicSharedMemorySize, fg_smem);
        cudaFuncSetAttribute(fps_kernel,              cudaFuncAttributeMaxDynamicSharedMemorySize, fps_smem);
    }

    // ---- capture fork: root event on the capture-origin stream ----
    cudaEventRecord(eRoot, 0);
    cudaStreamWaitEvent(sB, eRoot, 0);
    cudaStreamWaitEvent(sC, eRoot, 0);

    // stream B: feature pre-GEMM (independent of FPS)
    featgemm2_kernel<<<dim3(N_ / 128, B_), 256, fg_smem, sB>>>(feat, w0[0], w1[0], fp0, fp1);
    cudaEventRecord(eFG, sB);

    // stream 0: FPS -> ballquery
    fps_kernel<<<B_, 1024, fps_smem>>>(xyz, newxyz);
    ballquery_kernel<<<dim3(S_ / 64, B_), 512>>>(xyz, newxyz, idx0, idx1);
    cudaEventRecord(eBQ, 0);

    // stream C: scale-1 chain
    cudaStreamWaitEvent(sC, eBQ, 0);
    cudaStreamWaitEvent(sC, eFG, 0);
    group2_kernel<K1_><<<M1_ / 128, 256, 0, sC>>>(xyz, newxyz, fp1, w1[0], idx1, a1, st1);
    affine_kernel<<<1, 128, 0, sC>>>(g1[0], b1[0], st1, af1, 64, 1.0f / M1_);
    mma_kernel<64, 96, 0><<<M1_ / 128, 256, shb(64, 96), sC>>>(a1, w1[1], b1buf, nullptr, nullptr, af1, st1);
    affine_kernel<<<1, 128, 0, sC>>>(g1[1], b1[1], st1, af1, 96, 1.0f / M1_);
    mma_kernel<96, 128, 32><<<M1_ / 128, 256, shb(96, 128), sC>>>(b1buf, w1[2], nullptr, gmx1, gmn1, af1, st1);
    affine_kernel<<<1, 128, 0, sC>>>(g1[2], b1[2], st1, af1, 128, 1.0f / M1_);
    pool2_kernel<<<dim3(S_ / 32, B_), 256, 0, sC>>>(gmx1, gmn1, outfeat, 128, af1);
    cudaEventRecord(eS1, sC);

    // stream 0: scale-0 chain
    cudaStreamWaitEvent(0, eFG, 0);
    group2_kernel<K0_><<<M0_ / 128, 256>>>(xyz, newxyz, fp0, w0[0], idx0, a0, st0);
    affine_kernel<<<1, 128>>>(g0[0], b0[0], st0, af0, 64, 1.0f / M0_);
    mma_kernel<64, 64, 0><<<M0_ / 128, 256, shb(64, 64)>>>(a0, w0[1], b0buf, nullptr, nullptr, af0, st0);
    affine_kernel<<<1, 128>>>(g0[1], b0[1], st0, af0, 64, 1.0f / M0_);
    mma_kernel<64, 128, 16><<<M0_ / 128, 256, shb(64, 128)>>>(b0buf, w0[2], nullptr, gmx0, gmn0, af0, st0);
    affine_kernel<<<1, 128>>>(g0[2], b0[2], st0, af0, 128, 1.0f / M0_);
    pool2_kernel<<<dim3(S_ / 32, B_), 256>>>(gmx0, gmn0, outfeat, 0, af0);

    // join side stream back into the capture-origin stream
    cudaStreamWaitEvent(0, eS1, 0);
}

// round 12
// speedup vs baseline: 1.2195x; 1.0571x over previous
#include <cuda_runtime.h>
#include <cuda_fp16.h>
#include <cstdint>

#define B_   16
#define N_   4096
#define C_   64
#define S_   1024
#define K0_  16
#define K1_  32
#define M0_  (B_ * S_ * K0_)   // 262144
#define M1_  (B_ * S_ * K1_)   // 524288
#define R0SQ 0.01f
#define R1SQ 0.04f
#define EPS_ 1e-5f

// ---------------- scratch (device globals) ----------------
__device__ __half g_fp0[B_ * N_ * C_];     // F' scale 0, fp16
__device__ __half g_fp1[B_ * N_ * C_];     // F' scale 1, fp16
__device__ int    g_idx0[B_ * S_ * K0_];
__device__ int    g_idx1[B_ * S_ * K1_];
__device__ __half g_a0[64u * 262144u];     // s0 layer0 out
__device__ __half g_b0[64u * 262144u];     // s0 layer1 out
__device__ __half g_a1[64u * 524288u];     // s1 layer0 out
__device__ __half g_b1[96u * 524288u];     // s1 layer1 out
__device__ float  g_gmx0[16384u * 128u];
__device__ float  g_gmn0[16384u * 128u];
__device__ float  g_gmx1[16384u * 128u];
__device__ float  g_gmn1[16384u * 128u];
__device__ float  g_stats6[6 * 256];       // 6 layers x (128 sum, 128 sumsq)

__device__ __forceinline__ float f2tf_f(float x) {
    uint32_t r;
    asm("cvt.rna.tf32.f32 %0, %1;" : "=r"(r) : "f"(x));
    return __uint_as_float(r);
}

__device__ __forceinline__ void mma_tf32(float* d, const uint32_t* a, const uint32_t* b) {
    asm volatile("mma.sync.aligned.m16n8k8.row.col.f32.tf32.tf32.f32 "
                 "{%0,%1,%2,%3}, {%4,%5,%6,%7}, {%8,%9}, {%0,%1,%2,%3};"
                 : "+f"(d[0]), "+f"(d[1]), "+f"(d[2]), "+f"(d[3])
                 : "r"(a[0]), "r"(a[1]), "r"(a[2]), "r"(a[3]), "r"(b[0]), "r"(b[1]));
}

// ---------------- zero stats (each replay, before any producer) ----------------
__global__ void zero6_kernel() {
    for (int i = threadIdx.x; i < 6 * 256; i += 256) g_stats6[i] = 0.0f;
}

// ---------------- FPS (redux-based reduction) ----------------
__global__ void fps_kernel(const float* __restrict__ xyz, float* __restrict__ newxyz)
{
    extern __shared__ float sm[];
    float* sx = sm; float* sy = sm + N_; float* sz = sm + 2 * N_;
    __shared__ unsigned sbits[2][32];
    __shared__ int      sidx[2][32];

    const int b = blockIdx.x;
    const int t = threadIdx.x;          // 1024
    const int lane = t & 31, wid = t >> 5;

    for (int i = t; i < N_; i += 1024) {
        const float* p = xyz + ((size_t)b * N_ + i) * 3;
        sx[i] = p[0]; sy[i] = p[1]; sz[i] = p[2];
    }
    __syncthreads();

    float px[4], py[4], pz[4], dist[4];
#pragma unroll
    for (int j = 0; j < 4; ++j) {
        int n = t + (j << 10);
        px[j] = sx[n]; py[j] = sy[n]; pz[j] = sz[n];
        dist[j] = 1e10f;
    }

    if (t == 0) {
        float* o = newxyz + (size_t)b * S_ * 3;
        o[0] = sx[0]; o[1] = sy[0]; o[2] = sz[0];
    }
    float lx = sx[0], ly = sy[0], lz = sz[0];

    int p_ = 0;
    for (int i = 1; i < S_; ++i) {
        float bv = -1.0f; int bi = 0;
#pragma unroll
        for (int j = 0; j < 4; ++j) {
            float dx = px[j] - lx, dy = py[j] - ly, dz = pz[j] - lz;
            float d = dx * dx + dy * dy + dz * dz;
            float nd = fminf(dist[j], d);
            dist[j] = nd;
            if (nd > bv) { bv = nd; bi = t + (j << 10); }
        }
        unsigned dbits = __float_as_uint(bv);
        unsigned wmax = __reduce_max_sync(0xffffffffu, dbits);
        unsigned cand = (dbits == wmax) ? (unsigned)bi : 0xffffffffu;
        unsigned widx = __reduce_min_sync(0xffffffffu, cand);
        if (lane == 0) { sbits[p_][wid] = wmax; sidx[p_][wid] = (int)widx; }
        __syncthreads();
        unsigned vb = sbits[p_][lane];
        int      vi = sidx[p_][lane];
        unsigned bmax = __reduce_max_sync(0xffffffffu, vb);
        unsigned c2 = (vb == bmax) ? (unsigned)vi : 0xffffffffu;
        int bsel = (int)__reduce_min_sync(0xffffffffu, c2);
        lx = sx[bsel]; ly = sy[bsel]; lz = sz[bsel];
        if (t == 0) {
            float* o = newxyz + ((size_t)b * S_ + i) * 3;
            o[0] = lx; o[1] = ly; o[2] = lz;
        }
        p_ ^= 1;
    }
}

// ---------------- combined feature pre-GEMM -> fp16 F' ----------------
__global__ __launch_bounds__(256) void featgemm2_kernel(
    const float* __restrict__ feat,
    const float* __restrict__ W0, const float* __restrict__ W1,
    __half* __restrict__ Fp0, __half* __restrict__ Fp1)
{
    extern __shared__ float sm[];
    float* Wt = sm;             // [64][65]
    float* Xs = Wt + 64 * 65;   // [64][128]
    const int tid = threadIdx.x;
    const int b = blockIdx.y;
    const int n0 = blockIdx.x * 128;

    for (int i = tid; i < 64 * 32; i += 256) {
        int k = i >> 5, q = i & 31;
        *(float4*)(Xs + k * 128 + q * 4) =
            *(const float4*)(feat + ((size_t)(b * 64 + k)) * N_ + n0 + q * 4);
    }

    const int mi = tid & 15, ci = tid >> 4;
#pragma unroll
    for (int s = 0; s < 2; ++s) {
        const float* W = s ? W1 : W0;
        __half* Fp = s ? Fp1 : Fp0;
        __syncthreads();
        for (int i = tid; i < 64 * 64; i += 256) {
            int co = i >> 6, k = i & 63;
            Wt[k * 65 + co] = W[co * 67 + 3 + k];
        }
        __syncthreads();

        float acc[4][8];
#pragma unroll
        for (int j = 0; j < 4; ++j)
#pragma unroll
            for (int r = 0; r < 8; ++r) acc[j][r] = 0.0f;

#pragma unroll 4
        for (int k = 0; k < 64; ++k) {
            float xf[8];
            *(float4*)xf       = *(const float4*)(Xs + k * 128 + mi * 8);
            *(float4*)(xf + 4) = *(const float4*)(Xs + k * 128 + mi * 8 + 4);
#pragma unroll
            for (int j = 0; j < 4; ++j) {
                float w = Wt[k * 65 + ci * 4 + j];
#pragma unroll
                for (int r = 0; r < 8; ++r) acc[j][r] = fmaf(w, xf[r], acc[j][r]);
            }
        }
#pragma unroll
        for (int r = 0; r < 8; ++r) {
            size_t row = (size_t)(b << 12) + n0 + mi * 8 + r;
            __half2 h0 = __floats2half2_rn(acc[0][r], acc[1][r]);
            __half2 h1 = __floats2half2_rn(acc[2][r], acc[3][r]);
            uint2 u = make_uint2(*(uint32_t*)&h0, *(uint32_t*)&h1);
            *(uint2*)(Fp + (row << 6) + ci * 4) = u;
        }
    }
}

// ---------------- fused ball query (conditional ballots) ----------------
__global__ void ballquery_kernel(const float* __restrict__ xyz,
                                 const float* __restrict__ newxyz,
                                 int* __restrict__ idx0, int* __restrict__ idx1)
{
    __shared__ float sx[N_], sy[N_], sz[N_];
    const int bb = blockIdx.y;
    const int tid = threadIdx.x;                 // 512
    const int lane = tid & 31, w = tid >> 5;

    for (int i = tid; i < N_ * 3; i += 512) {
        float v = xyz[(size_t)bb * N_ * 3 + i];
        int n = i / 3, d = i - n * 3;
        if (d == 0) sx[n] = v; else if (d == 1) sy[n] = v; else sz[n] = v;
    }
    __syncthreads();

    const unsigned ltmask = (1u << lane) - 1u;

    for (int cc = 0; cc < 4; ++cc) {
        int s_ = blockIdx.x * 64 + w * 4 + cc;
        const float* ctr = newxyz + ((size_t)bb * S_ + s_) * 3;
        float cx = ctr[0], cy = ctr[1], cz = ctr[2];
        int* o0 = idx0 + ((size_t)bb * S_ + s_) * K0_;
        int* o1 = idx1 + ((size_t)bb * S_ + s_) * K1_;
        int cnt0 = 0, cnt1 = 0, first0 = 0, first1 = 0;

        for (int base = 0; base < N_; base += 32) {
            int n = base + lane;
            float dx = sx[n] - cx, dy = sy[n] - cy, dz = sz[n] - cz;
            float d2 = dx * dx + dy * dy + dz * dz;
            if (cnt1 < K1_) {
                unsigned m1 = __ballot_sync(0xffffffffu, d2 < R1SQ);
                if (m1) {
                    if (cnt1 == 0) first1 = base + __ffs(m1) - 1;
                    int pos = cnt1 + __popc(m1 & ltmask);
                    if ((d2 < R1SQ) && pos < K1_) o1[pos] = n;
                    cnt1 += __popc(m1); if (cnt1 > K1_) cnt1 = K1_;
                }
            }
            if (cnt0 < K0_) {
                unsigned m0 = __ballot_sync(0xffffffffu, d2 < R0SQ);
                if (m0) {
                    if (cnt0 == 0) first0 = base + __ffs(m0) - 1;
                    int pos = cnt0 + __popc(m0 & ltmask);
                    if ((d2 < R0SQ) && pos < K0_) o0[pos] = n;
                    cnt0 += __popc(m0); if (cnt0 > K0_) cnt0 = K0_;
                }
            } else if (cnt1 >= K1_) {
                break;
            }
        }
        for (int pos = cnt0 + lane; pos < K0_; pos += 32) o0[pos] = first0;
        for (int pos = cnt1 + lane; pos < K1_; pos += 32) o1[pos] = first1;
    }
}

// ---------------- layer-0 gather (uint4 path) + fp32 BN stats ----------------
template <int K>
__global__ __launch_bounds__(256) void group2_kernel(
    const float* __restrict__ xyz, const float* __restrict__ newxyz,
    const __half* __restrict__ Fp, const float* __restrict__ W /*64x67*/,
    const int* __restrict__ idx, __half* __restrict__ Y, float* __restrict__ stats)
{
    constexpr int LK = (K == 16) ? 4 : 5;
    __shared__ float sms[64 * 132];
    __shared__ float swx[64], swy[64], swz[64];
    const int tid = threadIdx.x;
    const size_t m0 = (size_t)blockIdx.x * 128;

    if (tid < 64) {
        swx[tid] = W[tid * 67 + 0];
        swy[tid] = W[tid * 67 + 1];
        swz[tid] = W[tid * 67 + 2];
    }
    __syncthreads();

    {
        const int mloc = tid >> 1, half = tid & 1;
        const size_t m = m0 + mloc;
        const int n = idx[m];
        const int sflat = (int)(m >> LK);
        const int b = sflat >> 10;
        const float* ctr = newxyz + (size_t)sflat * 3;
        const float* p = xyz + ((size_t)(b << 12) + n) * 3;
        const float rx = p[0] - ctr[0], ry = p[1] - ctr[1], rz = p[2] - ctr[2];
        const uint4* f = (const uint4*)(Fp + (((size_t)(b << 12) + n) << 6) + half * 32);
        uint4* yv = (uint4*)(Y + m * 64 + half * 32);
#pragma unroll
        for (int q4 = 0; q4 < 4; ++q4) {
            uint4 u = f[q4];
            __half2 h0 = *(__half2*)&u.x;
            __half2 h1 = *(__half2*)&u.y;
            __half2 h2 = *(__half2*)&u.z;
            __half2 h3 = *(__half2*)&u.w;
            int c = half * 32 + q4 * 8;
            float o[8];
            o[0] = fmaf(swx[c + 0], rx, fmaf(swy[c + 0], ry, fmaf(swz[c + 0], rz, __low2float(h0))));
            o[1] = fmaf(swx[c + 1], rx, fmaf(swy[c + 1], ry, fmaf(swz[c + 1], rz, __high2float(h0))));
            o[2] = fmaf(swx[c + 2], rx, fmaf(swy[c + 2], ry, fmaf(swz[c + 2], rz, __low2float(h1))));
            o[3] = fmaf(swx[c + 3], rx, fmaf(swy[c + 3], ry, fmaf(swz[c + 3], rz, __high2float(h1))));
            o[4] = fmaf(swx[c + 4], rx, fmaf(swy[c + 4], ry, fmaf(swz[c + 4], rz, __low2float(h2))));
            o[5] = fmaf(swx[c + 5], rx, fmaf(swy[c + 5], ry, fmaf(swz[c + 5], rz, __high2float(h2))));
            o[6] = fmaf(swx[c + 6], rx, fmaf(swy[c + 6], ry, fmaf(swz[c + 6], rz, __low2float(h3))));
            o[7] = fmaf(swx[c + 7], rx, fmaf(swy[c + 7], ry, fmaf(swz[c + 7], rz, __high2float(h3))));
#pragma unroll
            for (int j = 0; j < 8; ++j) sms[(c + j) * 132 + mloc] = o[j];
            __half2 w0 = __floats2half2_rn(o[0], o[1]);
            __half2 w1 = __floats2half2_rn(o[2], o[3]);
            __half2 w2 = __floats2half2_rn(o[4], o[5]);
            __half2 w3 = __floats2half2_rn(o[6], o[7]);
            yv[q4] = make_uint4(*(uint32_t*)&w0, *(uint32_t*)&w1,
                                *(uint32_t*)&w2, *(uint32_t*)&w3);
        }
    }
    __syncthreads();

    {
        const int c = tid >> 2, part = tid & 3;
        float s = 0.0f, s2 = 0.0f;
        const float4* row = (const float4*)(sms + c * 132 + part * 32);
#pragma unroll
        for (int q = 0; q < 8; ++q) {
            float4 v = row[q];
            s  += v.x + v.y + v.z + v.w;
            s2 += v.x * v.x + v.y * v.y + v.z * v.z + v.w * v.w;
        }
        s  += __shfl_down_sync(0xffffffffu, s, 2);
        s  += __shfl_down_sync(0xffffffffu, s, 1);
        s2 += __shfl_down_sync(0xffffffffu, s2, 2);
        s2 += __shfl_down_sync(0xffffffffu, s2, 1);
        if (part == 0) {
            atomicAdd(&stats[c], s);
            atomicAdd(&stats[128 + c], s2);
        }
    }
}

// ---------------- tf32 MMA GEMM (M=128, mt=2), fp16 streams, consumer-side BN ----------------
template <int CIN, int COUT, int POOLK>
__global__ __launch_bounds__(256) void mma_kernel(
    const __half* __restrict__ X, const float* __restrict__ W,
    __half* __restrict__ Y, float* __restrict__ gmx, float* __restrict__ gmn,
    const float* __restrict__ stats_in, const float* __restrict__ gam,
    const float* __restrict__ bet, float invM, float* __restrict__ stats_out)
{
    constexpr int WCT = COUT / 16;
    constexpr int XP = CIN + 4;
    constexpr int WP = COUT + 8;
    extern __shared__ float sm[];
    float* Wt  = sm;                   // [CIN][WP]
    float* Xs  = Wt + CIN * WP;        // [128][XP]
    float* red = Xs + 128 * XP;        // [2*COUT]
    __shared__ float saff[256];
    const int tid = threadIdx.x;
    const size_t m0 = (size_t)blockIdx.x * 128;

    // consumer-side affine from producer stats
    if (tid < CIN) {
        float mean = stats_in[tid] * invM;
        float var  = stats_in[128 + tid] * invM - mean * mean;
        float a = gam[tid] * rsqrtf(var + EPS_);
        saff[tid] = a;
        saff[128 + tid] = bet[tid] - mean * a;
    }
    if (tid < 2 * COUT) red[tid] = 0.0f;

    for (int i = tid; i < CIN * COUT; i += 256) {
        int co = i / CIN, k = i - co * CIN;
        Wt[k * WP + co] = f2tf_f(W[i]);
    }
    __syncthreads();   // saff ready before X staging

    for (int i = tid; i < 128 * (CIN / 4); i += 256) {
        int row = i / (CIN / 4), c4 = i % (CIN / 4);
        int c = c4 * 4;
        uint2 u = *(const uint2*)(X + (m0 + row) * CIN + c);
        __half2 h0 = *(__half2*)&u.x;
        __half2 h1 = *(__half2*)&u.y;
        float4 o;
        o.x = f2tf_f(fmaxf(fmaf(__low2float(h0),  saff[c + 0], saff[128 + c + 0]), 0.0f));
        o.y = f2tf_f(fmaxf(fmaf(__high2float(h0), saff[c + 1], saff[128 + c + 1]), 0.0f));
        o.z = f2tf_f(fmaxf(fmaf(__low2float(h1),  saff[c + 2], saff[128 + c + 2]), 0.0f));
        o.w = f2tf_f(fmaxf(fmaf(__high2float(h1), saff[c + 3], saff[128 + c + 3]), 0.0f));
        *(float4*)(Xs + row * XP + c) = o;
    }
    __syncthreads();

    const int lane = tid & 31, w = tid >> 5;
    const int gid = lane >> 2, tig = lane & 3;
    const int wm = (w & 3) * 32;
    const int wc = (w >> 2) * (COUT / 2);

    float acc[2][WCT][4];
#pragma unroll
    for (int mt = 0; mt < 2; ++mt)
#pragma unroll
        for (int ct = 0; ct < WCT; ++ct)
#pragma unroll
            for (int r = 0; r < 4; ++r) acc[mt][ct][r] = 0.0f;

#pragma unroll
    for (int k0 = 0; k0 < CIN; k0 += 8) {
        uint32_t a[2][4];
#pragma unroll
        for (int mt = 0; mt < 2; ++mt) {
            int r = wm + mt * 16 + gid;
            a[mt][0] = __float_as_uint(Xs[r * XP + k0 + tig]);
            a[mt][1] = __float_as_uint(Xs[(r + 8) * XP + k0 + tig]);
            a[mt][2] = __float_as_uint(Xs[r * XP + k0 + tig + 4]);
            a[mt][3] = __float_as_uint(Xs[(r + 8) * XP + k0 + tig + 4]);
        }
        uint32_t bf[WCT][2];
#pragma unroll
        for (int ct = 0; ct < WCT; ++ct) {
            int co = wc + ct * 8 + gid;
            bf[ct][0] = __float_as_uint(Wt[(k0 + tig) * WP + co]);
            bf[ct][1] = __float_as_uint(Wt[(k0 + tig + 4) * WP + co]);
        }
#pragma unroll
        for (int mt = 0; mt < 2; ++mt)
#pragma unroll
            for (int ct = 0; ct < WCT; ++ct)
                mma_tf32(acc[mt][ct], a[mt], bf[ct]);
    }

#pragma unroll
    for (int ct = 0; ct < WCT; ++ct) {
        float se = 0, so = 0, qe = 0, qo = 0;
#pragma unroll
        for (int mt = 0; mt < 2; ++mt) {
            const float* d = acc[mt][ct];
            se += d[0] + d[2]; so += d[1] + d[3];
            qe += d[0] * d[0] + d[2] * d[2];
            qo += d[1] * d[1] + d[3] * d[3];
        }
#pragma unroll
        for (int off = 16; off >= 4; off >>= 1) {
            se += __shfl_down_sync(0xffffffffu, se, off);
            so += __shfl_down_sync(0xffffffffu, so, off);
            qe += __shfl_down_sync(0xffffffffu, qe, off);
            qo += __shfl_down_sync(0xffffffffu, qo, off);
        }
        if (gid == 0) {
            int co = wc + ct * 8 + tig * 2;
            atomicAdd(&red[co], se);
            atomicAdd(&red[co + 1], so);
            atomicAdd(&red[COUT + co], qe);
            atomicAdd(&red[COUT + co + 1], qo);
        }
    }

    if (POOLK == 0) {
#pragma unroll
        for (int mt = 0; mt < 2; ++mt)
#pragma unroll
            for (int ct = 0; ct < WCT; ++ct) {
                size_t m = m0 + wm + mt * 16 + gid;
                int co = wc + ct * 8 + tig * 2;
                const float* d = acc[mt][ct];
                __half2 h0 = __floats2half2_rn(d[0], d[1]);
                __half2 h1 = __floats2half2_rn(d[2], d[3]);
                *(__half2*)(Y + m * COUT + co)       = h0;
                *(__half2*)(Y + (m + 8) * COUT + co) = h1;
            }
    } else if (POOLK == 16) {
#pragma unroll
        for (int mt = 0; mt < 2; ++mt)
#pragma unroll
            for (int ct = 0; ct < WCT; ++ct) {
                const float* d = acc[mt][ct];
                float mxe = fmaxf(d[0], d[2]), mxo = fmaxf(d[1], d[3]);
                float mne = fminf(d[0], d[2]), mno = fminf(d[1], d[3]);
#pragma unroll
                for (int off = 16; off >= 4; off >>= 1) {
                    mxe = fmaxf(mxe, __shfl_down_sync(0xffffffffu, mxe, off));
                    mxo = fmaxf(mxo, __shfl_down_sync(0xffffffffu, mxo, off));
                    mne = fminf(mne, __shfl_down_sync(0xffffffffu, mne, off));
                    mno = fminf(mno, __shfl_down_sync(0xffffffffu, mno, off));
                }
                if (gid == 0) {
                    size_t g = (m0 + wm + mt * 16) >> 4;
                    int co = wc + ct * 8 + tig * 2;
                    *(float2*)(gmx + g * COUT + co) = make_float2(mxe, mxo);
                    *(float2*)(gmn + g * COUT + co) = make_float2(mne, mno);
                }
            }
    } else { // POOLK == 32
#pragma unroll
        for (int ct = 0; ct < WCT; ++ct) {
            float mxe = -1e30f, mxo = -1e30f, mne = 1e30f, mno = 1e30f;
#pragma unroll
            for (int mt = 0; mt < 2; ++mt) {
                const float* d = acc[mt][ct];
                mxe = fmaxf(mxe, fmaxf(d[0], d[2]));
                mxo = fmaxf(mxo, fmaxf(d[1], d[3]));
                mne = fminf(mne, fminf(d[0], d[2]));
                mno = fminf(mno, fminf(d[1], d[3]));
            }
#pragma unroll
            for (int off = 16; off >= 4; off >>= 1) {
                mxe = fmaxf(mxe, __shfl_down_sync(0xffffffffu, mxe, off));
                mxo = fmaxf(mxo, __shfl_down_sync(0xffffffffu, mxo, off));
                mne = fminf(mne, __shfl_down_sync(0xffffffffu, mne, off));
                mno = fminf(mno, __shfl_down_sync(0xffffffffu, mno, off));
            }
            if (gid == 0) {
                size_t g = (m0 + wm) >> 5;
                int co = wc + ct * 8 + tig * 2;
                *(float2*)(gmx + g * COUT + co) = make_float2(mxe, mxo);
                *(float2*)(gmn + g * COUT + co) = make_float2(mne, mno);
            }
        }
    }

    __syncthreads();
    if (tid < COUT) atomicAdd(&stats_out[tid], red[tid]);
    else if (tid < 2 * COUT) atomicAdd(&stats_out[128 + (tid - COUT)], red[tid]);
}

// ---------------- pooled affine+ReLU + transpose (consumer-side BN) ----------------
__global__ __launch_bounds__(256) void pool2_kernel(
    const float* __restrict__ gmx, const float* __restrict__ gmn,
    float* __restrict__ outfeat, int cbase,
    const float* __restrict__ stats_in, const float* __restrict__ gam,
    const float* __restrict__ bet, float invM)
{
    __shared__ float st[128][33];
    __shared__ float sa[128], sb2[128];
    const int b = blockIdx.y, s0 = blockIdx.x * 32;
    const int tid = threadIdx.x;
    if (tid < 128) {
        float mean = stats_in[tid] * invM;
        float var  = stats_in[128 + tid] * invM - mean * mean;
        float a = gam[tid] * rsqrtf(var + EPS_);
        sa[tid] = a;
        sb2[tid] = bet[tid] - mean * a;
    }
    __syncthreads();
    {
        int c = tid & 127, sh = tid >> 7;
        float a = sa[c], bb = sb2[c];
#pragma unroll
        for (int j = 0; j < 16; ++j) {
            int s = s0 + sh * 16 + j;
            size_t g = ((size_t)(b << 10) + s) * 128 + c;
            float v = (a > 0.0f) ? gmx[g] : gmn[g];
            st[c][sh * 16 + j] = fmaxf(fmaf(a, v, bb), 0.0f);
        }
    }
    __syncthreads();
    {
        int c = tid >> 1, part = tid & 1;
        float* dst = outfeat + (((size_t)(b * 256 + cbase + c)) << 10) + s0 + part * 16;
#pragma unroll
        for (int j = 0; j < 4; ++j) {
            int s = part * 16 + j * 4;
            *(float4*)(dst + j * 4) = make_float4(st[c][s], st[c][s + 1], st[c][s + 2], st[c][s + 3]);
        }
    }
}

// ---------------- host launch ----------------
extern "C" void kernel_launch(void* const* d_in, const int* in_sizes, int n_in,
                              void* d_out, int out_size)
{
    const float* xyz  = (const float*)d_in[0];
    const float* feat = (const float*)d_in[1];
    const float* w0[3] = { (const float*)d_in[2], (const float*)d_in[5], (const float*)d_in[8] };
    const float* g0[3] = { (const float*)d_in[3], (const float*)d_in[6], (const float*)d_in[9] };
    const float* b0[3] = { (const float*)d_in[4], (const float*)d_in[7], (const float*)d_in[10] };
    const float* w1[3] = { (const float*)d_in[11], (const float*)d_in[14], (const float*)d_in[17] };
    const float* g1[3] = { (const float*)d_in[12], (const float*)d_in[15], (const float*)d_in[18] };
    const float* b1[3] = { (const float*)d_in[13], (const float*)d_in[16], (const float*)d_in[19] };

    float* out = (float*)d_out;
    float* newxyz = out;
    float* outfeat = out + (size_t)B_ * S_ * 3;

    __half *a0, *b0buf, *a1, *b1buf, *fp0, *fp1;
    float *gmx0, *gmn0, *gmx1, *gmn1, *st6;
    int *idx0, *idx1;
    cudaGetSymbolAddress((void**)&a0, g_a0);
    cudaGetSymbolAddress((void**)&b0buf, g_b0);
    cudaGetSymbolAddress((void**)&a1, g_a1);
    cudaGetSymbolAddress((void**)&b1buf, g_b1);
    cudaGetSymbolAddress((void**)&fp0, g_fp0);
    cudaGetSymbolAddress((void**)&fp1, g_fp1);
    cudaGetSymbolAddress((void**)&gmx0, g_gmx0);
    cudaGetSymbolAddress((void**)&gmn0, g_gmn0);
    cudaGetSymbolAddress((void**)&gmx1, g_gmx1);
    cudaGetSymbolAddress((void**)&gmn1, g_gmn1);
    cudaGetSymbolAddress((void**)&st6, g_stats6);
    cudaGetSymbolAddress((void**)&idx0, g_idx0);
    cudaGetSymbolAddress((void**)&idx1, g_idx1);

    float* s0l0 = st6 + 0 * 256;  float* s0l1 = st6 + 1 * 256;  float* s0l2 = st6 + 2 * 256;
    float* s1l0 = st6 + 3 * 256;  float* s1l1 = st6 + 4 * 256;  float* s1l2 = st6 + 5 * 256;

    auto shb = [](int cin, int cout) { return (cin * (cout + 8) + 128 * (cin + 4) + 2 * cout) * 4; };
    const int fps_smem = 3 * N_ * 4;
    const int fg_smem = (64 * 65 + 64 * 128) * 4;

    static cudaStream_t sB = nullptr, sC = nullptr;
    static cudaEvent_t eRoot = nullptr, eFG = nullptr, eBQ = nullptr, eS1 = nullptr;
    if (!sB) {
        cudaStreamCreateWithFlags(&sB, cudaStreamNonBlocking);
        cudaStreamCreateWithFlags(&sC, cudaStreamNonBlocking);
        cudaEventCreateWithFlags(&eRoot, cudaEventDisableTiming);
        cudaEventCreateWithFlags(&eFG, cudaEventDisableTiming);
        cudaEventCreateWithFlags(&eBQ, cudaEventDisableTiming);
        cudaEventCreateWithFlags(&eS1, cudaEventDisableTiming);
        cudaFuncSetAttribute(mma_kernel<64, 64, 0>,   cudaFuncAttributeMaxDynamicSharedMemorySize, shb(64, 64));
        cudaFuncSetAttribute(mma_kernel<64, 96, 0>,   cudaFuncAttributeMaxDynamicSharedMemorySize, shb(64, 96));
        cudaFuncSetAttribute(mma_kernel<64, 128, 16>, cudaFuncAttributeMaxDynamicSharedMemorySize, shb(64, 128));
        cudaFuncSetAttribute(mma_kernel<96, 128, 32>, cudaFuncAttributeMaxDynamicSharedMemorySize, shb(96, 128));
        cudaFuncSetAttribute(featgemm2_kernel,        cudaFuncAttributeMaxDynamicSharedMemorySize, fg_smem);
        cudaFuncSetAttribute(fps_kernel,              cudaFuncAttributeMaxDynamicSharedMemorySize, fps_smem);
    }

    // ---- capture fork: root event on the capture-origin stream ----
    cudaEventRecord(eRoot, 0);
    cudaStreamWaitEvent(sB, eRoot, 0);
    cudaStreamWaitEvent(sC, eRoot, 0);

    // stream B: zero stats + feature pre-GEMM (independent of FPS)
    zero6_kernel<<<1, 256, 0, sB>>>();
    featgemm2_kernel<<<dim3(N_ / 128, B_), 256, fg_smem, sB>>>(feat, w0[0], w1[0], fp0, fp1);
    cudaEventRecord(eFG, sB);

    // stream 0: FPS -> ballquery
    fps_kernel<<<B_, 1024, fps_smem>>>(xyz, newxyz);
    ballquery_kernel<<<dim3(S_ / 64, B_), 512>>>(xyz, newxyz, idx0, idx1);
    cudaEventRecord(eBQ, 0);

    // stream C: scale-1 chain
    cudaStreamWaitEvent(sC, eBQ, 0);
    cudaStreamWaitEvent(sC, eFG, 0);
    group2_kernel<K1_><<<M1_ / 128, 256, 0, sC>>>(xyz, newxyz, fp1, w1[0], idx1, a1, s1l0);
    mma_kernel<64, 96, 0><<<M1_ / 128, 256, shb(64, 96), sC>>>(
        a1, w1[1], b1buf, nullptr, nullptr, s1l0, g1[0], b1[0], 1.0f / M1_, s1l1);
    mma_kernel<96, 128, 32><<<M1_ / 128, 256, shb(96, 128), sC>>>(
        b1buf, w1[2], nullptr, gmx1, gmn1, s1l1, g1[1], b1[1], 1.0f / M1_, s1l2);
    pool2_kernel<<<dim3(S_ / 32, B_), 256, 0, sC>>>(gmx1, gmn1, outfeat, 128, s1l2, g1[2], b1[2], 1.0f / M1_);
    cudaEventRecord(eS1, sC);

    // stream 0: scale-0 chain
    cudaStreamWaitEvent(0, eFG, 0);
    group2_kernel<K0_><<<M0_ / 128, 256>>>(xyz, newxyz, fp0, w0[0], idx0, a0, s0l0);
    mma_kernel<64, 64, 0><<<M0_ / 128, 256, shb(64, 64)>>>(
        a0, w0[1], b0buf, nullptr, nullptr, s0l0, g0[0], b0[0], 1.0f / M0_, s0l1);
    mma_kernel<64, 128, 16><<<M0_ / 128, 256, shb(64, 128)>>>(
        b0buf, w0[2], nullptr, gmx0, gmn0, s0l1, g0[1], b0[1], 1.0f / M0_, s0l2);
    pool2_kernel<<<dim3(S_ / 32, B_), 256>>>(gmx0, gmn0, outfeat, 0, s0l2, g0[2], b0[2], 1.0f / M0_);

    // join side stream back into the capture-origin stream
    cudaStreamWaitEvent(0, eS1, 0);
}

// round 15
// speedup vs baseline: 1.2544x; 1.0286x over previous
#include <cuda_runtime.h>
#include <cuda_fp16.h>
#include <cstdint>

#define B_   16
#define N_   4096
#define C_   64
#define S_   1024
#define K0_  16
#define K1_  32
#define M0_  (B_ * S_ * K0_)   // 262144
#define M1_  (B_ * S_ * K1_)   // 524288
#define R0SQ 0.01f
#define R1SQ 0.04f
#define EPS_ 1e-5f

// ---------------- scratch (device globals) ----------------
__device__ __half g_fp0[B_ * N_ * C_];     // F' scale 0, fp16
__device__ __half g_fp1[B_ * N_ * C_];     // F' scale 1, fp16
__device__ int    g_idx0[B_ * S_ * K0_];
__device__ int    g_idx1[B_ * S_ * K1_];
__device__ __half g_a0[64u * 262144u];     // s0 layer0 out
__device__ __half g_b0[64u * 262144u];     // s0 layer1 out
__device__ __half g_a1[64u * 524288u];     // s1 layer0 out
__device__ __half g_b1[96u * 524288u];     // s1 layer1 out
__device__ float  g_gmx0[16384u * 128u];
__device__ float  g_gmn0[16384u * 128u];
__device__ float  g_gmx1[16384u * 128u];
__device__ float  g_gmn1[16384u * 128u];
__device__ float  g_stats6[6 * 256];       // 6 layers x (128 sum, 128 sumsq)

__device__ __forceinline__ float f2tf_f(float x) {
    uint32_t r;
    asm("cvt.rna.tf32.f32 %0, %1;" : "=r"(r) : "f"(x));
    return __uint_as_float(r);
}

__device__ __forceinline__ void mma_tf32(float* d, const uint32_t* a, const uint32_t* b) {
    asm volatile("mma.sync.aligned.m16n8k8.row.col.f32.tf32.tf32.f32 "
                 "{%0,%1,%2,%3}, {%4,%5,%6,%7}, {%8,%9}, {%0,%1,%2,%3};"
                 : "+f"(d[0]), "+f"(d[1]), "+f"(d[2]), "+f"(d[3])
                 : "r"(a[0]), "r"(a[1]), "r"(a[2]), "r"(a[3]), "r"(b[0]), "r"(b[1]));
}

// ---------------- zero stats (each replay, before any producer) ----------------
__global__ void zero6_kernel() {
    for (int i = threadIdx.x; i < 6 * 256; i += 256) g_stats6[i] = 0.0f;
}

// ---------------- FPS (redux-based reduction) ----------------
__global__ void fps_kernel(const float* __restrict__ xyz, float* __restrict__ newxyz)
{
    extern __shared__ float sm[];
    float* sx = sm; float* sy = sm + N_; float* sz = sm + 2 * N_;
    __shared__ unsigned sbits[2][32];
    __shared__ int      sidx[2][32];

    const int b = blockIdx.x;
    const int t = threadIdx.x;          // 1024
    const int lane = t & 31, wid = t >> 5;

    for (int i = t; i < N_; i += 1024) {
        const float* p = xyz + ((size_t)b * N_ + i) * 3;
        sx[i] = p[0]; sy[i] = p[1]; sz[i] = p[2];
    }
    __syncthreads();

    float px[4], py[4], pz[4], dist[4];
#pragma unroll
    for (int j = 0; j < 4; ++j) {
        int n = t + (j << 10);
        px[j] = sx[n]; py[j] = sy[n]; pz[j] = sz[n];
        dist[j] = 1e10f;
    }

    if (t == 0) {
        float* o = newxyz + (size_t)b * S_ * 3;
        o[0] = sx[0]; o[1] = sy[0]; o[2] = sz[0];
    }
    float lx = sx[0], ly = sy[0], lz = sz[0];

    int p_ = 0;
    for (int i = 1; i < S_; ++i) {
        float bv = -1.0f; int bi = 0;
#pragma unroll
        for (int j = 0; j < 4; ++j) {
            float dx = px[j] - lx, dy = py[j] - ly, dz = pz[j] - lz;
            float d = dx * dx + dy * dy + dz * dz;
            float nd = fminf(dist[j], d);
            dist[j] = nd;
            if (nd > bv) { bv = nd; bi = t + (j << 10); }
        }
        unsigned dbits = __float_as_uint(bv);
        unsigned wmax = __reduce_max_sync(0xffffffffu, dbits);
        unsigned cand = (dbits == wmax) ? (unsigned)bi : 0xffffffffu;
        unsigned widx = __reduce_min_sync(0xffffffffu, cand);
        if (lane == 0) { sbits[p_][wid] = wmax; sidx[p_][wid] = (int)widx; }
        __syncthreads();
        unsigned vb = sbits[p_][lane];
        int      vi = sidx[p_][lane];
        unsigned bmax = __reduce_max_sync(0xffffffffu, vb);
        unsigned c2 = (vb == bmax) ? (unsigned)vi : 0xffffffffu;
        int bsel = (int)__reduce_min_sync(0xffffffffu, c2);
        lx = sx[bsel]; ly = sy[bsel]; lz = sz[bsel];
        if (t == 0) {
            float* o = newxyz + ((size_t)b * S_ + i) * 3;
            o[0] = lx; o[1] = ly; o[2] = lz;
        }
        p_ ^= 1;
    }
}

// ---------------- combined feature pre-GEMM -> fp16 F' ----------------
__global__ __launch_bounds__(256) void featgemm2_kernel(
    const float* __restrict__ feat,
    const float* __restrict__ W0, const float* __restrict__ W1,
    __half* __restrict__ Fp0, __half* __restrict__ Fp1)
{
    extern __shared__ float sm[];
    float* Wt = sm;             // [64][65]
    float* Xs = Wt + 64 * 65;   // [64][128]
    const int tid = threadIdx.x;
    const int b = blockIdx.y;
    const int n0 = blockIdx.x * 128;

    for (int i = tid; i < 64 * 32; i += 256) {
        int k = i >> 5, q = i & 31;
        *(float4*)(Xs + k * 128 + q * 4) =
            *(const float4*)(feat + ((size_t)(b * 64 + k)) * N_ + n0 + q * 4);
    }

    const int mi = tid & 15, ci = tid >> 4;
#pragma unroll
    for (int s = 0; s < 2; ++s) {
        const float* W = s ? W1 : W0;
        __half* Fp = s ? Fp1 : Fp0;
        __syncthreads();
        for (int i = tid; i < 64 * 64; i += 256) {
            int co = i >> 6, k = i & 63;
            Wt[k * 65 + co] = W[co * 67 + 3 + k];
        }
        __syncthreads();

        float acc[4][8];
#pragma unroll
        for (int j = 0; j < 4; ++j)
#pragma unroll
            for (int r = 0; r < 8; ++r) acc[j][r] = 0.0f;

#pragma unroll 4
        for (int k = 0; k < 64; ++k) {
            float xf[8];
            *(float4*)xf       = *(const float4*)(Xs + k * 128 + mi * 8);
            *(float4*)(xf + 4) = *(const float4*)(Xs + k * 128 + mi * 8 + 4);
#pragma unroll
            for (int j = 0; j < 4; ++j) {
                float w = Wt[k * 65 + ci * 4 + j];
#pragma unroll
                for (int r = 0; r < 8; ++r) acc[j][r] = fmaf(w, xf[r], acc[j][r]);
            }
        }
#pragma unroll
        for (int r = 0; r < 8; ++r) {
            size_t row = (size_t)(b << 12) + n0 + mi * 8 + r;
            __half2 h0 = __floats2half2_rn(acc[0][r], acc[1][r]);
            __half2 h1 = __floats2half2_rn(acc[2][r], acc[3][r]);
            uint2 u = make_uint2(*(uint32_t*)&h0, *(uint32_t*)&h1);
            *(uint2*)(Fp + (row << 6) + ci * 4) = u;
        }
    }
}

// ---------------- single-radius ball query ----------------
template <int KK>
__global__ void ballquery1_kernel(const float* __restrict__ xyz,
                                  const float* __restrict__ newxyz,
                                  int* __restrict__ idx, float rsq)
{
    __shared__ float sx[N_], sy[N_], sz[N_];
    const int bb = blockIdx.y;
    const int tid = threadIdx.x;                 // 512
    const int lane = tid & 31, w = tid >> 5;

    for (int i = tid; i < N_ * 3; i += 512) {
        float v = xyz[(size_t)bb * N_ * 3 + i];
        int n = i / 3, d = i - n * 3;
        if (d == 0) sx[n] = v; else if (d == 1) sy[n] = v; else sz[n] = v;
    }
    __syncthreads();

    const unsigned ltmask = (1u << lane) - 1u;

    for (int cc = 0; cc < 4; ++cc) {
        int s_ = blockIdx.x * 64 + w * 4 + cc;
        const float* ctr = newxyz + ((size_t)bb * S_ + s_) * 3;
        float cx = ctr[0], cy = ctr[1], cz = ctr[2];
        int* o = idx + ((size_t)bb * S_ + s_) * KK;
        int cnt = 0, first = 0;

        for (int base = 0; base < N_; base += 32) {
            int n = base + lane;
            float dx = sx[n] - cx, dy = sy[n] - cy, dz = sz[n] - cz;
            float d2 = dx * dx + dy * dy + dz * dz;
            unsigned m = __ballot_sync(0xffffffffu, d2 < rsq);
            if (m) {
                if (cnt == 0) first = base + __ffs(m) - 1;
                int pos = cnt + __popc(m & ltmask);
                if ((d2 < rsq) && pos < KK) o[pos] = n;
                cnt += __popc(m);
                if (cnt >= KK) break;
            }
        }
        if (cnt > KK) cnt = KK;
        for (int pos = cnt + lane; pos < KK; pos += 32) o[pos] = first;
    }
}

// ---------------- layer-0 gather (uint4 path) + fp32 BN stats ----------------
template <int K>
__global__ __launch_bounds__(256) void group2_kernel(
    const float* __restrict__ xyz, const float* __restrict__ newxyz,
    const __half* __restrict__ Fp, const float* __restrict__ W /*64x67*/,
    const int* __restrict__ idx, __half* __restrict__ Y, float* __restrict__ stats)
{
    constexpr int LK = (K == 16) ? 4 : 5;
    __shared__ float sms[64 * 132];
    __shared__ float swx[64], swy[64], swz[64];
    const int tid = threadIdx.x;
    const size_t m0 = (size_t)blockIdx.x * 128;

    if (tid < 64) {
        swx[tid] = W[tid * 67 + 0];
        swy[tid] = W[tid * 67 + 1];
        swz[tid] = W[tid * 67 + 2];
    }
    __syncthreads();

    {
        const int mloc = tid >> 1, half = tid & 1;
        const size_t m = m0 + mloc;
        const int n = idx[m];
        const int sflat = (int)(m >> LK);
        const int b = sflat >> 10;
        const float* ctr = newxyz + (size_t)sflat * 3;
        const float* p = xyz + ((size_t)(b << 12) + n) * 3;
        const float rx = p[0] - ctr[0], ry = p[1] - ctr[1], rz = p[2] - ctr[2];
        const uint4* f = (const uint4*)(Fp + (((size_t)(b << 12) + n) << 6) + half * 32);
        uint4* yv = (uint4*)(Y + m * 64 + half * 32);
#pragma unroll
        for (int q4 = 0; q4 < 4; ++q4) {
            uint4 u = f[q4];
            __half2 h0 = *(__half2*)&u.x;
            __half2 h1 = *(__half2*)&u.y;
            __half2 h2 = *(__half2*)&u.z;
            __half2 h3 = *(__half2*)&u.w;
            int c = half * 32 + q4 * 8;
            float o[8];
            o[0] = fmaf(swx[c + 0], rx, fmaf(swy[c + 0], ry, fmaf(swz[c + 0], rz, __low2float(h0))));
            o[1] = fmaf(swx[c + 1], rx, fmaf(swy[c + 1], ry, fmaf(swz[c + 1], rz, __high2float(h0))));
            o[2] = fmaf(swx[c + 2], rx, fmaf(swy[c + 2], ry, fmaf(swz[c + 2], rz, __low2float(h1))));
            o[3] = fmaf(swx[c + 3], rx, fmaf(swy[c + 3], ry, fmaf(swz[c + 3], rz, __high2float(h1))));
            o[4] = fmaf(swx[c + 4], rx, fmaf(swy[c + 4], ry, fmaf(swz[c + 4], rz, __low2float(h2))));
            o[5] = fmaf(swx[c + 5], rx, fmaf(swy[c + 5], ry, fmaf(swz[c + 5], rz, __high2float(h2))));
            o[6] = fmaf(swx[c + 6], rx, fmaf(swy[c + 6], ry, fmaf(swz[c + 6], rz, __low2float(h3))));
            o[7] = fmaf(swx[c + 7], rx, fmaf(swy[c + 7], ry, fmaf(swz[c + 7], rz, __high2float(h3))));
#pragma unroll
            for (int j = 0; j < 8; ++j) sms[(c + j) * 132 + mloc] = o[j];
            __half2 w0 = __floats2half2_rn(o[0], o[1]);
            __half2 w1 = __floats2half2_rn(o[2], o[3]);
            __half2 w2 = __floats2half2_rn(o[4], o[5]);
            __half2 w3 = __floats2half2_rn(o[6], o[7]);
            yv[q4] = make_uint4(*(uint32_t*)&w0, *(uint32_t*)&w1,
                                *(uint32_t*)&w2, *(uint32_t*)&w3);
        }
    }
    __syncthreads();

    {
        const int c = tid >> 2, part = tid & 3;
        float s = 0.0f, s2 = 0.0f;
        const float4* row = (const float4*)(sms + c * 132 + part * 32);
#pragma unroll
        for (int q = 0; q < 8; ++q) {
            float4 v = row[q];
            s  += v.x + v.y + v.z + v.w;
            s2 += v.x * v.x + v.y * v.y + v.z * v.z + v.w * v.w;
        }
        s  += __shfl_down_sync(0xffffffffu, s, 2);
        s  += __shfl_down_sync(0xffffffffu, s, 1);
        s2 += __shfl_down_sync(0xffffffffu, s2, 2);
        s2 += __shfl_down_sync(0xffffffffu, s2, 1);
        if (part == 0) {
            atomicAdd(&stats[c], s);
            atomicAdd(&stats[128 + c], s2);
        }
    }
}

// ---------------- tf32 MMA GEMM (M=128, mt=2), fp16 streams, consumer-side BN ----------------
template <int CIN, int COUT, int POOLK>
__global__ __launch_bounds__(256) void mma_kernel(
    const __half* __restrict__ X, const float* __restrict__ W,
    __half* __restrict__ Y, float* __restrict__ gmx, float* __restrict__ gmn,
    const float* __restrict__ stats_in, const float* __restrict__ gam,
    const float* __restrict__ bet, float invM, float* __restrict__ stats_out)
{
    constexpr int WCT = COUT / 16;
    constexpr int XP = CIN + 4;
    constexpr int WP = COUT + 8;
    extern __shared__ float sm[];
    float* Wt  = sm;                   // [CIN][WP]
    float* Xs  = Wt + CIN * WP;        // [128][XP]
    float* red = Xs + 128 * XP;        // [2*COUT]
    __shared__ float saff[256];
    const int tid = threadIdx.x;
    const size_t m0 = (size_t)blockIdx.x * 128;

    if (tid < CIN) {
        float mean = stats_in[tid] * invM;
        float var  = stats_in[128 + tid] * invM - mean * mean;
        float a = gam[tid] * rsqrtf(var + EPS_);
        saff[tid] = a;
        saff[128 + tid] = bet[tid] - mean * a;
    }
    if (tid < 2 * COUT) red[tid] = 0.0f;

    for (int i = tid; i < CIN * COUT; i += 256) {
        int co = i / CIN, k = i - co * CIN;
        Wt[k * WP + co] = f2tf_f(W[i]);
    }
    __syncthreads();   // saff ready before X staging

    for (int i = tid; i < 128 * (CIN / 4); i += 256) {
        int row = i / (CIN / 4), c4 = i % (CIN / 4);
        int c = c4 * 4;
        uint2 u = *(const uint2*)(X + (m0 + row) * CIN + c);
        __half2 h0 = *(__half2*)&u.x;
        __half2 h1 = *(__half2*)&u.y;
        float4 o;
        o.x = f2tf_f(fmaxf(fmaf(__low2float(h0),  saff[c + 0], saff[128 + c + 0]), 0.0f));
        o.y = f2tf_f(fmaxf(fmaf(__high2float(h0), saff[c + 1], saff[128 + c + 1]), 0.0f));
        o.z = f2tf_f(fmaxf(fmaf(__low2float(h1),  saff[c + 2], saff[128 + c + 2]), 0.0f));
        o.w = f2tf_f(fmaxf(fmaf(__high2float(h1), saff[c + 3], saff[128 + c + 3]), 0.0f));
        *(float4*)(Xs + row * XP + c) = o;
    }
    __syncthreads();

    const int lane = tid & 31, w = tid >> 5;
    const int gid = lane >> 2, tig = lane & 3;
    const int wm = (w & 3) * 32;
    const int wc = (w >> 2) * (COUT / 2);

    float acc[2][WCT][4];
#pragma unroll
    for (int mt = 0; mt < 2; ++mt)
#pragma unroll
        for (int ct = 0; ct < WCT; ++ct)
#pragma unroll
            for (int r = 0; r < 4; ++r) acc[mt][ct][r] = 0.0f;

#pragma unroll
    for (int k0 = 0; k0 < CIN; k0 += 8) {
        uint32_t a[2][4];
#pragma unroll
        for (int mt = 0; mt < 2; ++mt) {
            int r = wm + mt * 16 + gid;
            a[mt][0] = __float_as_uint(Xs[r * XP + k0 + tig]);
            a[mt][1] = __float_as_uint(Xs[(r + 8) * XP + k0 + tig]);
            a[mt][2] = __float_as_uint(Xs[r * XP + k0 + tig + 4]);
            a[mt][3] = __float_as_uint(Xs[(r + 8) * XP + k0 + tig + 4]);
        }
        uint32_t bf[WCT][2];
#pragma unroll
        for (int ct = 0; ct < WCT; ++ct) {
            int co = wc + ct * 8 + gid;
            bf[ct][0] = __float_as_uint(Wt[(k0 + tig) * WP + co]);
            bf[ct][1] = __float_as_uint(Wt[(k0 + tig + 4) * WP + co]);
        }
#pragma unroll
        for (int mt = 0; mt < 2; ++mt)
#pragma unroll
            for (int ct = 0; ct < WCT; ++ct)
                mma_tf32(acc[mt][ct], a[mt], bf[ct]);
    }

#pragma unroll
    for (int ct = 0; ct < WCT; ++ct) {
        float se = 0, so = 0, qe = 0, qo = 0;
#pragma unroll
        for (int mt = 0; mt < 2; ++mt) {
            const float* d = acc[mt][ct];
            se += d[0] + d[2]; so += d[1] + d[3];
            qe += d[0] * d[0] + d[2] * d[2];
            qo += d[1] * d[1] + d[3] * d[3];
        }
#pragma unroll
        for (int off = 16; off >= 4; off >>= 1) {
            se += __shfl_down_sync(0xffffffffu, se, off);
            so += __shfl_down_sync(0xffffffffu, so, off);
            qe += __shfl_down_sync(0xffffffffu, qe, off);
            qo += __shfl_down_sync(0xffffffffu, qo, off);
        }
        if (gid == 0) {
            int co = wc + ct * 8 + tig * 2;
            atomicAdd(&red[co], se);
            atomicAdd(&red[co + 1], so);
            atomicAdd(&red[COUT + co], qe);
            atomicAdd(&red[COUT + co + 1], qo);
        }
    }

    if (POOLK == 0) {
#pragma unroll
        for (int mt = 0; mt < 2; ++mt)
#pragma unroll
            for (int ct = 0; ct < WCT; ++ct) {
                size_t m = m0 + wm + mt * 16 + gid;
                int co = wc + ct * 8 + tig * 2;
                const float* d = acc[mt][ct];
                __half2 h0 = __floats2half2_rn(d[0], d[1]);
                __half2 h1 = __floats2half2_rn(d[2], d[3]);
                *(__half2*)(Y + m * COUT + co)       = h0;
                *(__half2*)(Y + (m + 8) * COUT + co) = h1;
            }
    } else if (POOLK == 16) {
#pragma unroll
        for (int mt = 0; mt < 2; ++mt)
#pragma unroll
            for (int ct = 0; ct < WCT; ++ct) {
                const float* d = acc[mt][ct];
                float mxe = fmaxf(d[0], d[2]), mxo = fmaxf(d[1], d[3]);
                float mne = fminf(d[0], d[2]), mno = fminf(d[1], d[3]);
#pragma unroll
                for (int off = 16; off >= 4; off >>= 1) {
                    mxe = fmaxf(mxe, __shfl_down_sync(0xffffffffu, mxe, off));
                    mxo = fmaxf(mxo, __shfl_down_sync(0xffffffffu, mxo, off));
                    mne = fminf(mne, __shfl_down_sync(0xffffffffu, mne, off));
                    mno = fminf(mno, __shfl_down_sync(0xffffffffu, mno, off));
                }
                if (gid == 0) {
                    size_t g = (m0 + wm + mt * 16) >> 4;
                    int co = wc + ct * 8 + tig * 2;
                    *(float2*)(gmx + g * COUT + co) = make_float2(mxe, mxo);
                    *(float2*)(gmn + g * COUT + co) = make_float2(mne, mno);
                }
            }
    } else { // POOLK == 32
#pragma unroll
        for (int ct = 0; ct < WCT; ++ct) {
            float mxe = -1e30f, mxo = -1e30f, mne = 1e30f, mno = 1e30f;
#pragma unroll
            for (int mt = 0; mt < 2; ++mt) {
                const float* d = acc[mt][ct];
                mxe = fmaxf(mxe, fmaxf(d[0], d[2]));
                mxo = fmaxf(mxo, fmaxf(d[1], d[3]));
                mne = fminf(mne, fminf(d[0], d[2]));
                mno = fminf(mno, fminf(d[1], d[3]));
            }
#pragma unroll
            for (int off = 16; off >= 4; off >>= 1) {
                mxe = fmaxf(mxe, __shfl_down_sync(0xffffffffu, mxe, off));
                mxo = fmaxf(mxo, __shfl_down_sync(0xffffffffu, mxo, off));
                mne = fminf(mne, __shfl_down_sync(0xffffffffu, mne, off));
                mno = fminf(mno, __shfl_down_sync(0xffffffffu, mno, off));
            }
            if (gid == 0) {
                size_t g = (m0 + wm) >> 5;
                int co = wc + ct * 8 + tig * 2;
                *(float2*)(gmx + g * COUT + co) = make_float2(mxe, mxo);
                *(float2*)(gmn + g * COUT + co) = make_float2(mne, mno);
            }
        }
    }

    __syncthreads();
    if (tid < COUT) atomicAdd(&stats_out[tid], red[tid]);
    else if (tid < 2 * COUT) atomicAdd(&stats_out[128 + (tid - COUT)], red[tid]);
}

// ---------------- pooled affine+ReLU + transpose (consumer-side BN) ----------------
__global__ __launch_bounds__(256) void pool2_kernel(
    const float* __restrict__ gmx, const float* __restrict__ gmn,
    float* __restrict__ outfeat, int cbase,
    const float* __restrict__ stats_in, const float* __restrict__ gam,
    const float* __restrict__ bet, float invM)
{
    __shared__ float st[128][33];
    __shared__ float sa[128], sb2[128];
    const int b = blockIdx.y, s0 = blockIdx.x * 32;
    const int tid = threadIdx.x;
    if (tid < 128) {
        float mean = stats_in[tid] * invM;
        float var  = stats_in[128 + tid] * invM - mean * mean;
        float a = gam[tid] * rsqrtf(var + EPS_);
        sa[tid] = a;
        sb2[tid] = bet[tid] - mean * a;
    }
    __syncthreads();
    {
        int c = tid & 127, sh = tid >> 7;
        float a = sa[c], bb = sb2[c];
#pragma unroll
        for (int j = 0; j < 16; ++j) {
            int s = s0 + sh * 16 + j;
            size_t g = ((size_t)(b << 10) + s) * 128 + c;
            float v = (a > 0.0f) ? gmx[g] : gmn[g];
            st[c][sh * 16 + j] = fmaxf(fmaf(a, v, bb), 0.0f);
        }
    }
    __syncthreads();
    {
        int c = tid >> 1, part = tid & 1;
        float* dst = outfeat + (((size_t)(b * 256 + cbase + c)) << 10) + s0 + part * 16;
#pragma unroll
        for (int j = 0; j < 4; ++j) {
            int s = part * 16 + j * 4;
            *(float4*)(dst + j * 4) = make_float4(st[c][s], st[c][s + 1], st[c][s + 2], st[c][s + 3]);
        }
    }
}

// ---------------- host launch ----------------
extern "C" void kernel_launch(void* const* d_in, const int* in_sizes, int n_in,
                              void* d_out, int out_size)
{
    const float* xyz  = (const float*)d_in[0];
    const float* feat = (const float*)d_in[1];
    const float* w0[3] = { (const float*)d_in[2], (const float*)d_in[5], (const float*)d_in[8] };
    const float* g0[3] = { (const float*)d_in[3], (const float*)d_in[6], (const float*)d_in[9] };
    const float* b0[3] = { (const float*)d_in[4], (const float*)d_in[7], (const float*)d_in[10] };
    const float* w1[3] = { (const float*)d_in[11], (const float*)d_in[14], (const float*)d_in[17] };
    const float* g1[3] = { (const float*)d_in[12], (const float*)d_in[15], (const float*)d_in[18] };
    const float* b1[3] = { (const float*)d_in[13], (const float*)d_in[16], (const float*)d_in[19] };

    float* out = (float*)d_out;
    float* newxyz = out;
    float* outfeat = out + (size_t)B_ * S_ * 3;

    __half *a0, *b0buf, *a1, *b1buf, *fp0, *fp1;
    float *gmx0, *gmn0, *gmx1, *gmn1, *st6;
    int *idx0, *idx1;
    cudaGetSymbolAddress((void**)&a0, g_a0);
    cudaGetSymbolAddress((void**)&b0buf, g_b0);
    cudaGetSymbolAddress((void**)&a1, g_a1);
    cudaGetSymbolAddress((void**)&b1buf, g_b1);
    cudaGetSymbolAddress((void**)&fp0, g_fp0);
    cudaGetSymbolAddress((void**)&fp1, g_fp1);
    cudaGetSymbolAddress((void**)&gmx0, g_gmx0);
    cudaGetSymbolAddress((void**)&gmn0, g_gmn0);
    cudaGetSymbolAddress((void**)&gmx1, g_gmx1);
    cudaGetSymbolAddress((void**)&gmn1, g_gmn1);
    cudaGetSymbolAddress((void**)&st6, g_stats6);
    cudaGetSymbolAddress((void**)&idx0, g_idx0);
    cudaGetSymbolAddress((void**)&idx1, g_idx1);

    float* s0l0 = st6 + 0 * 256;  float* s0l1 = st6 + 1 * 256;  float* s0l2 = st6 + 2 * 256;
    float* s1l0 = st6 + 3 * 256;  float* s1l1 = st6 + 4 * 256;  float* s1l2 = st6 + 5 * 256;

    auto shb = [](int cin, int cout) { return (cin * (cout + 8) + 128 * (cin + 4) + 2 * cout) * 4; };
    const int fps_smem = 3 * N_ * 4;
    const int fg_smem = (64 * 65 + 64 * 128) * 4;

    static cudaStream_t sB = nullptr, sC = nullptr;
    static cudaEvent_t eRoot = nullptr, eFG = nullptr, eFPS = nullptr, eS1 = nullptr;
    if (!sB) {
        cudaStreamCreateWithFlags(&sB, cudaStreamNonBlocking);
        cudaStreamCreateWithFlags(&sC, cudaStreamNonBlocking);
        cudaEventCreateWithFlags(&eRoot, cudaEventDisableTiming);
        cudaEventCreateWithFlags(&eFG, cudaEventDisableTiming);
        cudaEventCreateWithFlags(&eFPS, cudaEventDisableTiming);
        cudaEventCreateWithFlags(&eS1, cudaEventDisableTiming);
        cudaFuncSetAttribute(mma_kernel<64, 64, 0>,   cudaFuncAttributeMaxDynamicSharedMemorySize, shb(64, 64));
        cudaFuncSetAttribute(mma_kernel<64, 96, 0>,   cudaFuncAttributeMaxDynamicSharedMemorySize, shb(64, 96));
        cudaFuncSetAttribute(mma_kernel<64, 128, 16>, cudaFuncAttributeMaxDynamicSharedMemorySize, shb(64, 128));
        cudaFuncSetAttribute(mma_kernel<96, 128, 32>, cudaFuncAttributeMaxDynamicSharedMemorySize, shb(96, 128));
        cudaFuncSetAttribute(featgemm2_kernel,        cudaFuncAttributeMaxDynamicSharedMemorySize, fg_smem);
        cudaFuncSetAttribute(fps_kernel,              cudaFuncAttributeMaxDynamicSharedMemorySize, fps_smem);
    }

    // ---- capture fork: root event on the capture-origin stream ----
    cudaEventRecord(eRoot, 0);
    cudaStreamWaitEvent(sB, eRoot, 0);
    cudaStreamWaitEvent(sC, eRoot, 0);

    // stream B: zero stats + feature pre-GEMM (independent of FPS)
    zero6_kernel<<<1, 256, 0, sB>>>();
    featgemm2_kernel<<<dim3(N_ / 128, B_), 256, fg_smem, sB>>>(feat, w0[0], w1[0], fp0, fp1);
    cudaEventRecord(eFG, sB);

    // stream 0: FPS
    fps_kernel<<<B_, 1024, fps_smem>>>(xyz, newxyz);
    cudaEventRecord(eFPS, 0);

    // stream C: scale-1 chain (bq1 finishes fast -> chain starts early)
    cudaStreamWaitEvent(sC, eFPS, 0);
    ballquery1_kernel<K1_><<<dim3(S_ / 64, B_), 512, 0, sC>>>(xyz, newxyz, idx1, R1SQ);
    cudaStreamWaitEvent(sC, eFG, 0);
    group2_kernel<K1_><<<M1_ / 128, 256, 0, sC>>>(xyz, newxyz, fp1, w1[0], idx1, a1, s1l0);
    mma_kernel<64, 96, 0><<<M1_ / 128, 256, shb(64, 96), sC>>>(
        a1, w1[1], b1buf, nullptr, nullptr, s1l0, g1[0], b1[0], 1.0f / M1_, s1l1);
    mma_kernel<96, 128, 32><<<M1_ / 128, 256, shb(96, 128), sC>>>(
        b1buf, w1[2], nullptr, gmx1, gmn1, s1l1, g1[1], b1[1], 1.0f / M1_, s1l2);
    pool2_kernel<<<dim3(S_ / 32, B_), 256, 0, sC>>>(gmx1, gmn1, outfeat, 128, s1l2, g1[2], b1[2], 1.0f / M1_);
    cudaEventRecord(eS1, sC);

    // stream 0: scale-0 chain (bq0 is the long scan; s0 chain is the short one)
    ballquery1_kernel<K0_><<<dim3(S_ / 64, B_), 512>>>(xyz, newxyz, idx0, R0SQ);
    cudaStreamWaitEvent(0, eFG, 0);
    group2_kernel<K0_><<<M0_ / 128, 256>>>(xyz, newxyz, fp0, w0[0], idx0, a0, s0l0);
    mma_kernel<64, 64, 0><<<M0_ / 128, 256, shb(64, 64)>>>(
        a0, w0[1], b0buf, nullptr, nullptr, s0l0, g0[0], b0[0], 1.0f / M0_, s0l1);
    mma_kernel<64, 128, 16><<<M0_ / 128, 256, shb(64, 128)>>>(
        b0buf, w0[2], nullptr, gmx0, gmn0, s0l1, g0[1], b0[1], 1.0f / M0_, s0l2);
    pool2_kernel<<<dim3(S_ / 32, B_), 256>>>(gmx0, gmn0, outfeat, 0, s0l2, g0[2], b0[2], 1.0f / M0_);

    // join side stream back into the capture-origin stream
    cudaStreamWaitEvent(0, eS1, 0);
}

// round 16
// speedup vs baseline: 1.2911x; 1.0293x over previous
#include <cuda_runtime.h>
#include <cuda_fp16.h>
#include <cstdint>

#define B_   16
#define N_   4096
#define C_   64
#define S_   1024
#define K0_  16
#define K1_  32
#define M0_  (B_ * S_ * K0_)   // 262144
#define M1_  (B_ * S_ * K1_)   // 524288
#define R0SQ 0.01f
#define R1SQ 0.04f
#define EPS_ 1e-5f

// ---------------- scratch (device globals) ----------------
__device__ __half g_fp0[B_ * N_ * C_];     // F' scale 0, fp16
__device__ __half g_fp1[B_ * N_ * C_];     // F' scale 1, fp16
__device__ int    g_idx0[B_ * S_ * K0_];
__device__ int    g_idx1[B_ * S_ * K1_];
__device__ __half g_a0[64u * 262144u];     // s0 layer0 out
__device__ __half g_b0[64u * 262144u];     // s0 layer1 out
__device__ __half g_a1[64u * 524288u];     // s1 layer0 out
__device__ __half g_b1[96u * 524288u];     // s1 layer1 out
__device__ float  g_gmx0[16384u * 128u];
__device__ float  g_gmn0[16384u * 128u];
__device__ float  g_gmx1[16384u * 128u];
__device__ float  g_gmn1[16384u * 128u];
__device__ float  g_stats6[6 * 256];       // 6 layers x (128 sum, 128 sumsq)

__device__ __forceinline__ void mma_tf32(float* d, const uint32_t* a, const uint32_t* b) {
    asm volatile("mma.sync.aligned.m16n8k8.row.col.f32.tf32.tf32.f32 "
                 "{%0,%1,%2,%3}, {%4,%5,%6,%7}, {%8,%9}, {%0,%1,%2,%3};"
                 : "+f"(d[0]), "+f"(d[1]), "+f"(d[2]), "+f"(d[3])
                 : "r"(a[0]), "r"(a[1]), "r"(a[2]), "r"(a[3]), "r"(b[0]), "r"(b[1]));
}

// ---------------- zero stats (each replay, before any producer) ----------------
__global__ void zero6_kernel() {
    for (int i = threadIdx.x; i < 6 * 256; i += 256) g_stats6[i] = 0.0f;
}

// ---------------- FPS (redux-based reduction) ----------------
__global__ void fps_kernel(const float* __restrict__ xyz, float* __restrict__ newxyz)
{
    extern __shared__ float sm[];
    float* sx = sm; float* sy = sm + N_; float* sz = sm + 2 * N_;
    __shared__ unsigned sbits[2][32];
    __shared__ int      sidx[2][32];

    const int b = blockIdx.x;
    const int t = threadIdx.x;          // 1024
    const int lane = t & 31, wid = t >> 5;

    for (int i = t; i < N_; i += 1024) {
        const float* p = xyz + ((size_t)b * N_ + i) * 3;
        sx[i] = p[0]; sy[i] = p[1]; sz[i] = p[2];
    }
    __syncthreads();

    float px[4], py[4], pz[4], dist[4];
#pragma unroll
    for (int j = 0; j < 4; ++j) {
        int n = t + (j << 10);
        px[j] = sx[n]; py[j] = sy[n]; pz[j] = sz[n];
        dist[j] = 1e10f;
    }

    if (t == 0) {
        float* o = newxyz + (size_t)b * S_ * 3;
        o[0] = sx[0]; o[1] = sy[0]; o[2] = sz[0];
    }
    float lx = sx[0], ly = sy[0], lz = sz[0];

    int p_ = 0;
    for (int i = 1; i < S_; ++i) {
        float bv = -1.0f; int bi = 0;
#pragma unroll
        for (int j = 0; j < 4; ++j) {
            float dx = px[j] - lx, dy = py[j] - ly, dz = pz[j] - lz;
            float d = dx * dx + dy * dy + dz * dz;
            float nd = fminf(dist[j], d);
            dist[j] = nd;
            if (nd > bv) { bv = nd; bi = t + (j << 10); }
        }
        unsigned dbits = __float_as_uint(bv);
        unsigned wmax = __reduce_max_sync(0xffffffffu, dbits);
        unsigned cand = (dbits == wmax) ? (unsigned)bi : 0xffffffffu;
        unsigned widx = __reduce_min_sync(0xffffffffu, cand);
        if (lane == 0) { sbits[p_][wid] = wmax; sidx[p_][wid] = (int)widx; }
        __syncthreads();
        unsigned vb = sbits[p_][lane];
        int      vi = sidx[p_][lane];
        unsigned bmax = __reduce_max_sync(0xffffffffu, vb);
        unsigned c2 = (vb == bmax) ? (unsigned)vi : 0xffffffffu;
        int bsel = (int)__reduce_min_sync(0xffffffffu, c2);
        lx = sx[bsel]; ly = sy[bsel]; lz = sz[bsel];
        if (t == 0) {
            float* o = newxyz + ((size_t)b * S_ + i) * 3;
            o[0] = lx; o[1] = ly; o[2] = lz;
        }
        p_ ^= 1;
    }
}

// ---------------- combined feature pre-GEMM -> fp16 F' ----------------
__global__ __launch_bounds__(256) void featgemm2_kernel(
    const float* __restrict__ feat,
    const float* __restrict__ W0, const float* __restrict__ W1,
    __half* __restrict__ Fp0, __half* __restrict__ Fp1)
{
    extern __shared__ float sm[];
    float* Wt = sm;             // [64][65]
    float* Xs = Wt + 64 * 65;   // [64][128]
    const int tid = threadIdx.x;
    const int b = blockIdx.y;
    const int n0 = blockIdx.x * 128;

    for (int i = tid; i < 64 * 32; i += 256) {
        int k = i >> 5, q = i & 31;
        *(float4*)(Xs + k * 128 + q * 4) =
            *(const float4*)(feat + ((size_t)(b * 64 + k)) * N_ + n0 + q * 4);
    }

    const int mi = tid & 15, ci = tid >> 4;
#pragma unroll
    for (int s = 0; s < 2; ++s) {
        const float* W = s ? W1 : W0;
        __half* Fp = s ? Fp1 : Fp0;
        __syncthreads();
        for (int i = tid; i < 64 * 64; i += 256) {
            int co = i >> 6, k = i & 63;
            Wt[k * 65 + co] = W[co * 67 + 3 + k];
        }
        __syncthreads();

        float acc[4][8];
#pragma unroll
        for (int j = 0; j < 4; ++j)
#pragma unroll
            for (int r = 0; r < 8; ++r) acc[j][r] = 0.0f;

#pragma unroll 4
        for (int k = 0; k < 64; ++k) {
            float xf[8];
            *(float4*)xf       = *(const float4*)(Xs + k * 128 + mi * 8);
            *(float4*)(xf + 4) = *(const float4*)(Xs + k * 128 + mi * 8 + 4);
#pragma unroll
            for (int j = 0; j < 4; ++j) {
                float w = Wt[k * 65 + ci * 4 + j];
#pragma unroll
                for (int r = 0; r < 8; ++r) acc[j][r] = fmaf(w, xf[r], acc[j][r]);
            }
        }
#pragma unroll
        for (int r = 0; r < 8; ++r) {
            size_t row = (size_t)(b << 12) + n0 + mi * 8 + r;
            __half2 h0 = __floats2half2_rn(acc[0][r], acc[1][r]);
            __half2 h1 = __floats2half2_rn(acc[2][r], acc[3][r]);
            uint2 u = make_uint2(*(uint32_t*)&h0, *(uint32_t*)&h1);
            *(uint2*)(Fp + (row << 6) + ci * 4) = u;
        }
    }
}

// ---------------- single-radius ball query ----------------
template <int KK>
__global__ void ballquery1_kernel(const float* __restrict__ xyz,
                                  const float* __restrict__ newxyz,
                                  int* __restrict__ idx, float rsq)
{
    __shared__ float sx[N_], sy[N_], sz[N_];
    const int bb = blockIdx.y;
    const int tid = threadIdx.x;                 // 512
    const int lane = tid & 31, w = tid >> 5;

    for (int i = tid; i < N_ * 3; i += 512) {
        float v = xyz[(size_t)bb * N_ * 3 + i];
        int n = i / 3, d = i - n * 3;
        if (d == 0) sx[n] = v; else if (d == 1) sy[n] = v; else sz[n] = v;
    }
    __syncthreads();

    const unsigned ltmask = (1u << lane) - 1u;

    for (int cc = 0; cc < 4; ++cc) {
        int s_ = blockIdx.x * 64 + w * 4 + cc;
        const float* ctr = newxyz + ((size_t)bb * S_ + s_) * 3;
        float cx = ctr[0], cy = ctr[1], cz = ctr[2];
        int* o = idx + ((size_t)bb * S_ + s_) * KK;
        int cnt = 0, first = 0;

        for (int base = 0; base < N_; base += 32) {
            int n = base + lane;
            float dx = sx[n] - cx, dy = sy[n] - cy, dz = sz[n] - cz;
            float d2 = dx * dx + dy * dy + dz * dz;
            unsigned m = __ballot_sync(0xffffffffu, d2 < rsq);
            if (m) {
                if (cnt == 0) first = base + __ffs(m) - 1;
                int pos = cnt + __popc(m & ltmask);
                if ((d2 < rsq) && pos < KK) o[pos] = n;
                cnt += __popc(m);
                if (cnt >= KK) break;
            }
        }
        if (cnt > KK) cnt = KK;
        for (int pos = cnt + lane; pos < KK; pos += 32) o[pos] = first;
    }
}

// ---------------- layer-0 gather (uint4 path) + fp32 BN stats ----------------
template <int K>
__global__ __launch_bounds__(256) void group2_kernel(
    const float* __restrict__ xyz, const float* __restrict__ newxyz,
    const __half* __restrict__ Fp, const float* __restrict__ W /*64x67*/,
    const int* __restrict__ idx, __half* __restrict__ Y, float* __restrict__ stats)
{
    constexpr int LK = (K == 16) ? 4 : 5;
    __shared__ float sms[64 * 132];
    __shared__ float swx[64], swy[64], swz[64];
    const int tid = threadIdx.x;
    const size_t m0 = (size_t)blockIdx.x * 128;

    if (tid < 64) {
        swx[tid] = W[tid * 67 + 0];
        swy[tid] = W[tid * 67 + 1];
        swz[tid] = W[tid * 67 + 2];
    }
    __syncthreads();

    {
        const int mloc = tid >> 1, half = tid & 1;
        const size_t m = m0 + mloc;
        const int n = idx[m];
        const int sflat = (int)(m >> LK);
        const int b = sflat >> 10;
        const float* ctr = newxyz + (size_t)sflat * 3;
        const float* p = xyz + ((size_t)(b << 12) + n) * 3;
        const float rx = p[0] - ctr[0], ry = p[1] - ctr[1], rz = p[2] - ctr[2];
        const uint4* f = (const uint4*)(Fp + (((size_t)(b << 12) + n) << 6) + half * 32);
        uint4* yv = (uint4*)(Y + m * 64 + half * 32);
#pragma unroll
        for (int q4 = 0; q4 < 4; ++q4) {
            uint4 u = f[q4];
            __half2 h0 = *(__half2*)&u.x;
            __half2 h1 = *(__half2*)&u.y;
            __half2 h2 = *(__half2*)&u.z;
            __half2 h3 = *(__half2*)&u.w;
            int c = half * 32 + q4 * 8;
            float o[8];
            o[0] = fmaf(swx[c + 0], rx, fmaf(swy[c + 0], ry, fmaf(swz[c + 0], rz, __low2float(h0))));
            o[1] = fmaf(swx[c + 1], rx, fmaf(swy[c + 1], ry, fmaf(swz[c + 1], rz, __high2float(h0))));
            o[2] = fmaf(swx[c + 2], rx, fmaf(swy[c + 2], ry, fmaf(swz[c + 2], rz, __low2float(h1))));
            o[3] = fmaf(swx[c + 3], rx, fmaf(swy[c + 3], ry, fmaf(swz[c + 3], rz, __high2float(h1))));
            o[4] = fmaf(swx[c + 4], rx, fmaf(swy[c + 4], ry, fmaf(swz[c + 4], rz, __low2float(h2))));
            o[5] = fmaf(swx[c + 5], rx, fmaf(swy[c + 5], ry, fmaf(swz[c + 5], rz, __high2float(h2))));
            o[6] = fmaf(swx[c + 6], rx, fmaf(swy[c + 6], ry, fmaf(swz[c + 6], rz, __low2float(h3))));
            o[7] = fmaf(swx[c + 7], rx, fmaf(swy[c + 7], ry, fmaf(swz[c + 7], rz, __high2float(h3))));
#pragma unroll
            for (int j = 0; j < 8; ++j) sms[(c + j) * 132 + mloc] = o[j];
            __half2 w0 = __floats2half2_rn(o[0], o[1]);
            __half2 w1 = __floats2half2_rn(o[2], o[3]);
            __half2 w2 = __floats2half2_rn(o[4], o[5]);
            __half2 w3 = __floats2half2_rn(o[6], o[7]);
            yv[q4] = make_uint4(*(uint32_t*)&w0, *(uint32_t*)&w1,
                                *(uint32_t*)&w2, *(uint32_t*)&w3);
        }
    }
    __syncthreads();

    {
        const int c = tid >> 2, part = tid & 3;
        float s = 0.0f, s2 = 0.0f;
        const float4* row = (const float4*)(sms + c * 132 + part * 32);
#pragma unroll
        for (int q = 0; q < 8; ++q) {
            float4 v = row[q];
            s  += v.x + v.y + v.z + v.w;
            s2 += v.x * v.x + v.y * v.y + v.z * v.z + v.w * v.w;
        }
        s  += __shfl_down_sync(0xffffffffu, s, 2);
        s  += __shfl_down_sync(0xffffffffu, s, 1);
        s2 += __shfl_down_sync(0xffffffffu, s2, 2);
        s2 += __shfl_down_sync(0xffffffffu, s2, 1);
        if (part == 0) {
            atomicAdd(&stats[c], s);
            atomicAdd(&stats[128 + c], s2);
        }
    }
}

// ---------------- tf32 MMA GEMM (M=128, mt=2), fp16 smem staging for 2x occupancy ----------------
template <int CIN, int COUT, int POOLK>
__global__ __launch_bounds__(256) void mma_kernel(
    const __half* __restrict__ X, const float* __restrict__ W,
    __half* __restrict__ Y, float* __restrict__ gmx, float* __restrict__ gmn,
    const float* __restrict__ stats_in, const float* __restrict__ gam,
    const float* __restrict__ bet, float invM, float* __restrict__ stats_out)
{
    constexpr int WCT = COUT / 16;
    constexpr int XPh = CIN + 8;       // half stride; row byte stride mod 128 -> conflict-free
    constexpr int WPh = COUT + 8;      // half stride
    extern __shared__ char smc[];
    __half* Wt  = (__half*)smc;                        // [CIN][WPh] fp16
    __half* Xs  = (__half*)(smc + CIN * WPh * 2);      // [128][XPh] fp16
    float*  red = (float*)(smc + CIN * WPh * 2 + 128 * XPh * 2);  // [2*COUT]
    __shared__ float saff[256];
    const int tid = threadIdx.x;
    const size_t m0 = (size_t)blockIdx.x * 128;

    if (tid < CIN) {
        float mean = stats_in[tid] * invM;
        float var  = stats_in[128 + tid] * invM - mean * mean;
        float a = gam[tid] * rsqrtf(var + EPS_);
        saff[tid] = a;
        saff[128 + tid] = bet[tid] - mean * a;
    }
    if (tid < 2 * COUT) red[tid] = 0.0f;

    for (int i = tid; i < CIN * COUT; i += 256) {
        int co = i / CIN, k = i - co * CIN;
        Wt[k * WPh + co] = __float2half_rn(W[i]);
    }
    __syncthreads();   // saff ready before X staging

    for (int i = tid; i < 128 * (CIN / 4); i += 256) {
        int row = i / (CIN / 4), c4 = i % (CIN / 4);
        int c = c4 * 4;
        uint2 u = *(const uint2*)(X + (m0 + row) * CIN + c);
        __half2 h0 = *(__half2*)&u.x;
        __half2 h1 = *(__half2*)&u.y;
        float e0 = fmaxf(fmaf(__low2float(h0),  saff[c + 0], saff[128 + c + 0]), 0.0f);
        float e1 = fmaxf(fmaf(__high2float(h0), saff[c + 1], saff[128 + c + 1]), 0.0f);
        float e2 = fmaxf(fmaf(__low2float(h1),  saff[c + 2], saff[128 + c + 2]), 0.0f);
        float e3 = fmaxf(fmaf(__high2float(h1), saff[c + 3], saff[128 + c + 3]), 0.0f);
        __half2 o0 = __floats2half2_rn(e0, e1);
        __half2 o1 = __floats2half2_rn(e2, e3);
        *(uint2*)(Xs + row * XPh + c) = make_uint2(*(uint32_t*)&o0, *(uint32_t*)&o1);
    }
    __syncthreads();

    const int lane = tid & 31, w = tid >> 5;
    const int gid = lane >> 2, tig = lane & 3;
    const int wm = (w & 3) * 32;
    const int wc = (w >> 2) * (COUT / 2);

    float acc[2][WCT][4];
#pragma unroll
    for (int mt = 0; mt < 2; ++mt)
#pragma unroll
        for (int ct = 0; ct < WCT; ++ct)
#pragma unroll
            for (int r = 0; r < 4; ++r) acc[mt][ct][r] = 0.0f;

#pragma unroll
    for (int k0 = 0; k0 < CIN; k0 += 8) {
        uint32_t a[2][4];
#pragma unroll
        for (int mt = 0; mt < 2; ++mt) {
            int r = wm + mt * 16 + gid;
            a[mt][0] = __float_as_uint(__half2float(Xs[r * XPh + k0 + tig]));
            a[mt][1] = __float_as_uint(__half2float(Xs[(r + 8) * XPh + k0 + tig]));
            a[mt][2] = __float_as_uint(__half2float(Xs[r * XPh + k0 + tig + 4]));
            a[mt][3] = __float_as_uint(__half2float(Xs[(r + 8) * XPh + k0 + tig + 4]));
        }
        uint32_t bf[WCT][2];
#pragma unroll
        for (int ct = 0; ct < WCT; ++ct) {
            int co = wc + ct * 8 + gid;
            bf[ct][0] = __float_as_uint(__half2float(Wt[(k0 + tig) * WPh + co]));
            bf[ct][1] = __float_as_uint(__half2float(Wt[(k0 + tig + 4) * WPh + co]));
        }
#pragma unroll
        for (int mt = 0; mt < 2; ++mt)
#pragma unroll
            for (int ct = 0; ct < WCT; ++ct)
                mma_tf32(acc[mt][ct], a[mt], bf[ct]);
    }

#pragma unroll
    for (int ct = 0; ct < WCT; ++ct) {
        float se = 0, so = 0, qe = 0, qo = 0;
#pragma unroll
        for (int mt = 0; mt < 2; ++mt) {
            const float* d = acc[mt][ct];
            se += d[0] + d[2]; so += d[1] + d[3];
            qe += d[0] * d[0] + d[2] * d[2];
            qo += d[1] * d[1] + d[3] * d[3];
        }
#pragma unroll
        for (int off = 16; off >= 4; off >>= 1) {
            se += __shfl_down_sync(0xffffffffu, se, off);
            so += __shfl_down_sync(0xffffffffu, so, off);
            qe += __shfl_down_sync(0xffffffffu, qe, off);
            qo += __shfl_down_sync(0xffffffffu, qo, off);
        }
        if (gid == 0) {
            int co = wc + ct * 8 + tig * 2;
            atomicAdd(&red[co], se);
            atomicAdd(&red[co + 1], so);
            atomicAdd(&red[COUT + co], qe);
            atomicAdd(&red[COUT + co + 1], qo);
        }
    }

    if (POOLK == 0) {
#pragma unroll
        for (int mt = 0; mt < 2; ++mt)
#pragma unroll
            for (int ct = 0; ct < WCT; ++ct) {
                size_t m = m0 + wm + mt * 16 + gid;
                int co = wc + ct * 8 + tig * 2;
                const float* d = acc[mt][ct];
                __half2 h0 = __floats2half2_rn(d[0], d[1]);
                __half2 h1 = __floats2half2_rn(d[2], d[3]);
                *(__half2*)(Y + m * COUT + co)       = h0;
                *(__half2*)(Y + (m + 8) * COUT + co) = h1;
            }
    } else if (POOLK == 16) {
#pragma unroll
        for (int mt = 0; mt < 2; ++mt)
#pragma unroll
            for (int ct = 0; ct < WCT; ++ct) {
                const float* d = acc[mt][ct];
                float mxe = fmaxf(d[0], d[2]), mxo = fmaxf(d[1], d[3]);
                float mne = fminf(d[0], d[2]), mno = fminf(d[1], d[3]);
#pragma unroll
                for (int off = 16; off >= 4; off >>= 1) {
                    mxe = fmaxf(mxe, __shfl_down_sync(0xffffffffu, mxe, off));
                    mxo = fmaxf(mxo, __shfl_down_sync(0xffffffffu, mxo, off));
                    mne = fminf(mne, __shfl_down_sync(0xffffffffu, mne, off));
                    mno = fminf(mno, __shfl_down_sync(0xffffffffu, mno, off));
                }
                if (gid == 0) {
                    size_t g = (m0 + wm + mt * 16) >> 4;
                    int co = wc + ct * 8 + tig * 2;
                    *(float2*)(gmx + g * COUT + co) = make_float2(mxe, mxo);
                    *(float2*)(gmn + g * COUT + co) = make_float2(mne, mno);
                }
            }
    } else { // POOLK == 32
#pragma unroll
        for (int ct = 0; ct < WCT; ++ct) {
            float mxe = -1e30f, mxo = -1e30f, mne = 1e30f, mno = 1e30f;
#pragma unroll
            for (int mt = 0; mt < 2; ++mt) {
                const float* d = acc[mt][ct];
                mxe = fmaxf(mxe, fmaxf(d[0], d[2]));
                mxo = fmaxf(mxo, fmaxf(d[1], d[3]));
                mne = fminf(mne, fminf(d[0], d[2]));
                mno = fminf(mno, fminf(d[1], d[3]));
            }
#pragma unroll
            for (int off = 16; off >= 4; off >>= 1) {
                mxe = fmaxf(mxe, __shfl_down_sync(0xffffffffu, mxe, off));
                mxo = fmaxf(mxo, __shfl_down_sync(0xffffffffu, mxo, off));
                mne = fminf(mne, __shfl_down_sync(0xffffffffu, mne, off));
                mno = fminf(mno, __shfl_down_sync(0xffffffffu, mno, off));
            }
            if (gid == 0) {
                size_t g = (m0 + wm) >> 5;
                int co = wc + ct * 8 + tig * 2;
                *(float2*)(gmx + g * COUT + co) = make_float2(mxe, mxo);
                *(float2*)(gmn + g * COUT + co) = make_float2(mne, mno);
            }
        }
    }

    __syncthreads();
    if (tid < COUT) atomicAdd(&stats_out[tid], red[tid]);
    else if (tid < 2 * COUT) atomicAdd(&stats_out[128 + (tid - COUT)], red[tid]);
}

// ---------------- pooled affine+ReLU + transpose (consumer-side BN) ----------------
__global__ __launch_bounds__(256) void pool2_kernel(
    const float* __restrict__ gmx, const float* __restrict__ gmn,
    float* __restrict__ outfeat, int cbase,
    const float* __restrict__ stats_in, const float* __restrict__ gam,
    const float* __restrict__ bet, float invM)
{
    __shared__ float st[128][33];
    __shared__ float sa[128], sb2[128];
    const int b = blockIdx.y, s0 = blockIdx.x * 32;
    const int tid = threadIdx.x;
    if (tid < 128) {
        float mean = stats_in[tid] * invM;
        float var  = stats_in[128 + tid] * invM - mean * mean;
        float a = gam[tid] * rsqrtf(var + EPS_);
        sa[tid] = a;
        sb2[tid] = bet[tid] - mean * a;
    }
    __syncthreads();
    {
        int c = tid & 127, sh = tid >> 7;
        float a = sa[c], bb = sb2[c];
#pragma unroll
        for (int j = 0; j < 16; ++j) {
            int s = s0 + sh * 16 + j;
            size_t g = ((size_t)(b << 10) + s) * 128 + c;
            float v = (a > 0.0f) ? gmx[g] : gmn[g];
            st[c][sh * 16 + j] = fmaxf(fmaf(a, v, bb), 0.0f);
        }
    }
    __syncthreads();
    {
        int c = tid >> 1, part = tid & 1;
        float* dst = outfeat + (((size_t)(b * 256 + cbase + c)) << 10) + s0 + part * 16;
#pragma unroll
        for (int j = 0; j < 4; ++j) {
            int s = part * 16 + j * 4;
            *(float4*)(dst + j * 4) = make_float4(st[c][s], st[c][s + 1], st[c][s + 2], st[c][s + 3]);
        }
    }
}

// ---------------- host launch ----------------
extern "C" void kernel_launch(void* const* d_in, const int* in_sizes, int n_in,
                              void* d_out, int out_size)
{
    const float* xyz  = (const float*)d_in[0];
    const float* feat = (const float*)d_in[1];
    const float* w0[3] = { (const float*)d_in[2], (const float*)d_in[5], (const float*)d_in[8] };
    const float* g0[3] = { (const float*)d_in[3], (const float*)d_in[6], (const float*)d_in[9] };
    const float* b0[3] = { (const float*)d_in[4], (const float*)d_in[7], (const float*)d_in[10] };
    const float* w1[3] = { (const float*)d_in[11], (const float*)d_in[14], (const float*)d_in[17] };
    const float* g1[3] = { (const float*)d_in[12], (const float*)d_in[15], (const float*)d_in[18] };
    const float* b1[3] = { (const float*)d_in[13], (const float*)d_in[16], (const float*)d_in[19] };

    float* out = (float*)d_out;
    float* newxyz = out;
    float* outfeat = out + (size_t)B_ * S_ * 3;

    __half *a0, *b0buf, *a1, *b1buf, *fp0, *fp1;
    float *gmx0, *gmn0, *gmx1, *gmn1, *st6;
    int *idx0, *idx1;
    cudaGetSymbolAddress((void**)&a0, g_a0);
    cudaGetSymbolAddress((void**)&b0buf, g_b0);
    cudaGetSymbolAddress((void**)&a1, g_a1);
    cudaGetSymbolAddress((void**)&b1buf, g_b1);
    cudaGetSymbolAddress((void**)&fp0, g_fp0);
    cudaGetSymbolAddress((void**)&fp1, g_fp1);
    cudaGetSymbolAddress((void**)&gmx0, g_gmx0);
    cudaGetSymbolAddress((void**)&gmn0, g_gmn0);
    cudaGetSymbolAddress((void**)&gmx1, g_gmx1);
    cudaGetSymbolAddress((void**)&gmn1, g_gmn1);
    cudaGetSymbolAddress((void**)&st6, g_stats6);
    cudaGetSymbolAddress((void**)&idx0, g_idx0);
    cudaGetSymbolAddress((void**)&idx1, g_idx1);

    float* s0l0 = st6 + 0 * 256;  float* s0l1 = st6 + 1 * 256;  float* s0l2 = st6 + 2 * 256;
    float* s1l0 = st6 + 3 * 256;  float* s1l1 = st6 + 4 * 256;  float* s1l2 = st6 + 5 * 256;

    auto shb = [](int cin, int cout) {
        return cin * (cout + 8) * 2 + 128 * (cin + 8) * 2 + 2 * cout * 4;
    };
    const int fps_smem = 3 * N_ * 4;
    const int fg_smem = (64 * 65 + 64 * 128) * 4;

    static cudaStream_t sB = nullptr, sC = nullptr;
    static cudaEvent_t eRoot = nullptr, eFG = nullptr, eFPS = nullptr, eS1 = nullptr;
    if (!sB) {
        cudaStreamCreateWithFlags(&sB, cudaStreamNonBlocking);
        cudaStreamCreateWithFlags(&sC, cudaStreamNonBlocking);
        cudaEventCreateWithFlags(&eRoot, cudaEventDisableTiming);
        cudaEventCreateWithFlags(&eFG, cudaEventDisableTiming);
        cudaEventCreateWithFlags(&eFPS, cudaEventDisableTiming);
        cudaEventCreateWithFlags(&eS1, cudaEventDisableTiming);
        cudaFuncSetAttribute(mma_kernel<64, 64, 0>,   cudaFuncAttributeMaxDynamicSharedMemorySize, shb(64, 64));
        cudaFuncSetAttribute(mma_kernel<64, 96, 0>,   cudaFuncAttributeMaxDynamicSharedMemorySize, shb(64, 96));
        cudaFuncSetAttribute(mma_kernel<64, 128, 16>, cudaFuncAttributeMaxDynamicSharedMemorySize, shb(64, 128));
        cudaFuncSetAttribute(mma_kernel<96, 128, 32>, cudaFuncAttributeMaxDynamicSharedMemorySize, shb(96, 128));
        cudaFuncSetAttribute(featgemm2_kernel,        cudaFuncAttributeMaxDynamicSharedMemorySize, fg_smem);
        cudaFuncSetAttribute(fps_kernel,              cudaFuncAttributeMaxDynamicSharedMemorySize, fps_smem);
    }

    // ---- capture fork: root event on the capture-origin stream ----
    cudaEventRecord(eRoot, 0);
    cudaStreamWaitEvent(sB, eRoot, 0);
    cudaStreamWaitEvent(sC, eRoot, 0);

    // stream B: zero stats + feature pre-GEMM (independent of FPS)
    zero6_kernel<<<1, 256, 0, sB>>>();
    featgemm2_kernel<<<dim3(N_ / 128, B_), 256, fg_smem, sB>>>(feat, w0[0], w1[0], fp0, fp1);
    cudaEventRecord(eFG, sB);

    // stream 0: FPS
    fps_kernel<<<B_, 1024, fps_smem>>>(xyz, newxyz);
    cudaEventRecord(eFPS, 0);

    // stream C: scale-1 chain (bq1 finishes fast -> chain starts early)
    cudaStreamWaitEvent(sC, eFPS, 0);
    ballquery1_kernel<K1_><<<dim3(S_ / 64, B_), 512, 0, sC>>>(xyz, newxyz, idx1, R1SQ);
    cudaStreamWaitEvent(sC, eFG, 0);
    group2_kernel<K1_><<<M1_ / 128, 256, 0, sC>>>(xyz, newxyz, fp1, w1[0], idx1, a1, s1l0);
    mma_kernel<64, 96, 0><<<M1_ / 128, 256, shb(64, 96), sC>>>(
        a1, w1[1], b1buf, nullptr, nullptr, s1l0, g1[0], b1[0], 1.0f / M1_, s1l1);
    mma_kernel<96, 128, 32><<<M1_ / 128, 256, shb(96, 128), sC>>>(
        b1buf, w1[2], nullptr, gmx1, gmn1, s1l1, g1[1], b1[1], 1.0f / M1_, s1l2);
    pool2_kernel<<<dim3(S_ / 32, B_), 256, 0, sC>>>(gmx1, gmn1, outfeat, 128, s1l2, g1[2], b1[2], 1.0f / M1_);
    cudaEventRecord(eS1, sC);

    // stream 0: scale-0 chain (bq0 is the long scan; s0 chain is the short one)
    ballquery1_kernel<K0_><<<dim3(S_ / 64, B_), 512>>>(xyz, newxyz, idx0, R0SQ);
    cudaStreamWaitEvent(0, eFG, 0);
    group2_kernel<K0_><<<M0_ / 128, 256>>>(xyz, newxyz, fp0, w0[0], idx0, a0, s0l0);
    mma_kernel<64, 64, 0><<<M0_ / 128, 256, shb(64, 64)>>>(
        a0, w0[1], b0buf, nullptr, nullptr, s0l0, g0[0], b0[0], 1.0f / M0_, s0l1);
    mma_kernel<64, 128, 16><<<M0_ / 128, 256, shb(64, 128)>>>(
        b0buf, w0[2], nullptr, gmx0, gmn0, s0l1, g0[1], b0[1], 1.0f / M0_, s0l2);
    pool2_kernel<<<dim3(S_ / 32, B_), 256>>>(gmx0, gmn0, outfeat, 0, s0l2, g0[2], b0[2], 1.0f / M0_);

    // join side stream back into the capture-origin stream
    cudaStreamWaitEvent(0, eS1, 0);
}